// round 9
// baseline (speedup 1.0000x reference)
#include <cuda_runtime.h>
#include <cuda_fp16.h>
#include <math.h>
#include <stdint.h>

// Problem constants
#define BB 512
#define TT 168
#define II 64
#define HH 256
#define GG 1024   // 4*H
#define BT (BB*TT)
#define GXR 1032  // staged gx smem row stride (floats)

// ---------------------------------------------------------------------------
// Scratch (device globals: allocation-free rule)
// ---------------------------------------------------------------------------
__device__ float g_gx[(size_t)BT * GG];   // gate pre-activations, interleaved gate layout
__device__ float g_out1[(size_t)BT * HH]; // layer-1 hidden outputs
__device__ float g_WT[HH * GG];           // W_ih transposed+interleaved (GEMM B)
__device__ __half g_WhhPh[HH * GG];       // W_hh fp16, scan B-fragment layout (see prep)
__device__ float g_bias[GG];              // b_ih+b_hh, interleaved

// Interleaving: column n = j*4+q maps to raw gate row r = q*256 + j
// (q: 0=i, 1=f, 2=g, 3=o).

// ---------------------------------------------------------------------------
// tf32 / fp16 mma / activation helpers
// ---------------------------------------------------------------------------
__device__ __forceinline__ uint32_t f2tf32(float x) {
    uint32_t r;
    asm("cvt.rna.tf32.f32 %0, %1;" : "=r"(r) : "f"(x));
    return r;
}

__device__ __forceinline__ void mma_tf32(float* c, const uint32_t* a, uint32_t b0, uint32_t b1) {
    asm volatile(
        "mma.sync.aligned.m16n8k8.row.col.f32.tf32.tf32.f32 "
        "{%0,%1,%2,%3}, {%4,%5,%6,%7}, {%8,%9}, {%0,%1,%2,%3};"
        : "+f"(c[0]), "+f"(c[1]), "+f"(c[2]), "+f"(c[3])
        : "r"(a[0]), "r"(a[1]), "r"(a[2]), "r"(a[3]), "r"(b0), "r"(b1));
}

// m16n8k16 fp16 inputs, fp32 accumulate
__device__ __forceinline__ void mma_f16(float* c, const uint32_t* a, uint32_t b0, uint32_t b1) {
    asm volatile(
        "mma.sync.aligned.m16n8k16.row.col.f32.f16.f16.f32 "
        "{%0,%1,%2,%3}, {%4,%5,%6,%7}, {%8,%9}, {%0,%1,%2,%3};"
        : "+f"(c[0]), "+f"(c[1]), "+f"(c[2]), "+f"(c[3])
        : "r"(a[0]), "r"(a[1]), "r"(a[2]), "r"(a[3]), "r"(b0), "r"(b1));
}

__device__ __forceinline__ float sigmoid_fast(float x) {
    return __fdividef(1.f, 1.f + __expf(-x));
}
__device__ __forceinline__ float tanh_fast(float x) {
    float xc = fminf(fmaxf(x, -15.f), 15.f);
    float e = __expf(-2.f * xc);
    return __fdividef(1.f - e, 1.f + e);
}

// ---------------------------------------------------------------------------
// Weight prep: transpose + gate-interleave + bias combine + scan W permute.
// Scan W fp16 layout (m16n8k16 B fragments): warp w of 16 owns n8-blocks
// nb in [w*8, w*8+8); pair p = 0..3, odd = nb&1. One uint4 = B-frags (uint2)
// of nb = w*8+p*2 and w*8+p*2+1 for one kblk (K=16):
//   word index = (((kblk*16 + w)*4 + p)*32 + lane)*4 + (odd*2 + ridx)
//   lane = (nin<<2) | ((kin&7)>>1), ridx = kin>>3, half = kin&1
// ---------------------------------------------------------------------------
__global__ void prep_weights(const float* __restrict__ W_ih,
                             const float* __restrict__ W_hh,
                             const float* __restrict__ b_ih,
                             const float* __restrict__ b_hh,
                             int K)
{
    int idx = blockIdx.x * 256 + threadIdx.x;  // 0 .. 256*1024-1
    int n = idx & (GG - 1);
    int k = idx >> 10;
    int j = n >> 2;
    int q = n & 3;
    int r = q * HH + j;
    if (k < K) g_WT[k * GG + n] = W_ih[r * K + k];

    {
        float wv = W_hh[r * HH + k];
        int nb = n >> 3, nin = n & 7;
        int w = nb >> 3, win = nb & 7, p = win >> 1, odd = win & 1;
        int kblk = k >> 4, kin = k & 15;
        int lane = (nin << 2) | ((kin & 7) >> 1);
        int ridx = kin >> 3;
        int hf   = kin & 1;
        size_t o = (((((size_t)(kblk * 16 + w) * 4 + p) * 32 + lane) * 4)
                    + (odd * 2 + ridx)) * 2 + hf;
        g_WhhPh[o] = __float2half_rn(wv);
    }
    if (k == 0) g_bias[n] = b_ih[r] + b_hh[r];
}

// ---------------------------------------------------------------------------
// Feed-forward GEMM (tensor cores, tf32): unchanged (validated R2-R7).
// ---------------------------------------------------------------------------
template <int K>
__global__ __launch_bounds__(256)
void gemm_gx_tf32(const float* __restrict__ X_in)
{
    const float* X = X_in ? X_in : (const float*)g_out1;
    constexpr int KT = K / 32;

    __shared__ uint32_t sA[2][4096];
    __shared__ uint32_t sB[2][2048];

    const int tid  = threadIdx.x;
    const int warp = tid >> 5;
    const int lane = tid & 31;
    const int m0 = blockIdx.x * 128;
    const int n0 = blockIdx.y * 64;
    const int wmb = (warp >> 1) * 2;
    const int wnb = (warp & 1) * 4;

    float acc[2][4][4];
#pragma unroll
    for (int i = 0; i < 2; i++)
#pragma unroll
        for (int j = 0; j < 4; j++)
#pragma unroll
            for (int q = 0; q < 4; q++) acc[i][j][q] = 0.f;

    float4 av[4];
    float4 bv[2];

    auto ldg_tile = [&](int kt) {
#pragma unroll
        for (int i = 0; i < 4; i++) {
            int v = tid + 256 * i;
            int row = v >> 3;
            int kc = (v & 7) * 4;
            av[i] = *(const float4*)(X + (size_t)(m0 + row) * K + kt * 32 + kc);
        }
#pragma unroll
        for (int i = 0; i < 2; i++) {
            int v = tid + 256 * i;
            int row = v >> 4;
            int nc = (v & 15) * 4;
            bv[i] = *(const float4*)(g_WT + (size_t)(kt * 32 + row) * GG + n0 + nc);
        }
    };

    auto sts_tile = [&](int buf) {
#pragma unroll
        for (int i = 0; i < 4; i++) {
            int v = tid + 256 * i;
            int row = v >> 3;
            int kc0 = (v & 7) * 4;
            int mblk = row >> 4, mr = row & 15;
            float f[4] = {av[i].x, av[i].y, av[i].z, av[i].w};
#pragma unroll
            for (int j = 0; j < 4; j++) {
                int kc = kc0 + j;
                int kblk = kc >> 3, kin = kc & 7;
                int t = ((mr & 7) << 2) | (kin & 3);
                int slot = ((kin >> 2) << 1) | (mr >> 3);
                sA[buf][(((kblk << 3) | mblk) << 7) + (t << 2) + slot] = f2tf32(f[j]);
            }
        }
#pragma unroll
        for (int i = 0; i < 2; i++) {
            int v = tid + 256 * i;
            int row = v >> 4;
            int nc0 = (v & 15) * 4;
            int kblk = row >> 3, kin = row & 7;
            float f[4] = {bv[i].x, bv[i].y, bv[i].z, bv[i].w};
#pragma unroll
            for (int j = 0; j < 4; j++) {
                int nc = nc0 + j;
                int nblk = nc >> 3, nin = nc & 7;
                int t = (nin << 2) | (kin & 3);
                int slot = kin >> 2;
                sB[buf][(((kblk << 3) | nblk) << 6) + (t << 1) + slot] = f2tf32(f[j]);
            }
        }
    };

    auto compute = [&](int buf) {
#pragma unroll
        for (int ks = 0; ks < 4; ks++) {
            uint32_t afr[2][4];
            uint32_t bfr[4][2];
#pragma unroll
            for (int mi = 0; mi < 2; mi++) {
                uint4 a = *(const uint4*)&sA[buf][(((ks << 3) | (wmb + mi)) << 7) + (lane << 2)];
                afr[mi][0] = a.x; afr[mi][1] = a.y; afr[mi][2] = a.z; afr[mi][3] = a.w;
            }
#pragma unroll
            for (int ni = 0; ni < 4; ni++) {
                uint2 b = *(const uint2*)&sB[buf][(((ks << 3) | (wnb + ni)) << 6) + (lane << 1)];
                bfr[ni][0] = b.x; bfr[ni][1] = b.y;
            }
#pragma unroll
            for (int mi = 0; mi < 2; mi++)
#pragma unroll
                for (int ni = 0; ni < 4; ni++)
                    mma_tf32(acc[mi][ni], afr[mi], bfr[ni][0], bfr[ni][1]);
        }
    };

    ldg_tile(0);
    sts_tile(0);
    __syncthreads();
#pragma unroll
    for (int kt = 0; kt < KT; kt++) {
        if (kt + 1 < KT) ldg_tile(kt + 1);
        compute(kt & 1);
        if (kt + 1 < KT) sts_tile((kt + 1) & 1);
        __syncthreads();
    }

    const int g = lane >> 2;
    const int cq = lane & 3;
#pragma unroll
    for (int ni = 0; ni < 4; ni++) {
        int gn = n0 + ((wnb + ni) << 3) + cq * 2;
        float bx = g_bias[gn];
        float by = g_bias[gn + 1];
#pragma unroll
        for (int mi = 0; mi < 2; mi++) {
            int gm = m0 + ((wmb + mi) << 4) + g;
            float2 r0 = make_float2(acc[mi][ni][0] + bx, acc[mi][ni][1] + by);
            float2 r1 = make_float2(acc[mi][ni][2] + bx, acc[mi][ni][3] + by);
            *(float2*)(g_gx + (size_t)gm * GG + gn) = r0;
            *(float2*)(g_gx + (size_t)(gm + 8) * GG + gn) = r1;
        }
    }
}

// ---------------------------------------------------------------------------
// Recurrent scan v5 (fp16 HMMA, fused register update).
// 32 CTAs x MB=16 rows, 512 threads (16 warps).
// - gates never leave registers: lane-pair shfl.xor(1) regroups the 4 gates
//   of each h-column in one thread (even lane -> row g, odd -> row g+8);
//   c-state lives in the mma thread's registers.
// - shA (h, fp16 A-fragments) double-buffered: read buf t&1, write buf (t+1)&1.
//   Buffer stride: 2048 u32 == 4096 halves.  (R8 bug: used 8192 -> smem OOB.)
// - gx cp.async TRIPLE-buffered (single barrier/step allows 1-epoch warp skew).
// - W ring-3 register prefetch; fast EX2/RCP activations; fp32 accumulate.
// ONE __syncthreads per step.
// ---------------------------------------------------------------------------
__global__ __launch_bounds__(512, 1)
void lstm_scan5(float* __restrict__ out_in)
{
    float* out = out_in ? out_in : (float*)g_out1;

    extern __shared__ float smem_f[];
    float* gxb[3] = { smem_f, smem_f + 16 * GXR, smem_f + 32 * GXR };   // 3x [16][GXR]
    uint32_t* shA = (uint32_t*)(smem_f + 48 * GXR);   // 2 x 2048 u32: [kblk16][lane32][word4]
    __half* shA_h = (__half*)shA;

    const int tid  = threadIdx.x;
    const int w    = tid >> 5;
    const int lane = tid & 31;
    const int g    = lane >> 2;
    const int cq   = lane & 3;
    const int pr   = cq & 1;          // 0: update row g, 1: row g+8
    const int b0   = blockIdx.x * 16;

    // fused-update constants: thread (w, lane) owns h columns j = w*16 + ni*2 + (cq>>1)
    const int jlo  = w * 16 + (cq >> 1);            // + ni*2
    const int hf   = cq >> 1;                       // half index within fp16 pair
    const size_t outBase0 = ((size_t)(b0 + g + pr * 8) * TT) * HH + jlo;

    for (int i = tid; i < 4096; i += 512) shA[i] = 0u;
    float cst[8];
#pragma unroll
    for (int i = 0; i < 8; i++) cst[i] = 0.f;
    __syncthreads();

    const uint4* __restrict__ Wp = (const uint4*)g_WhhPh;

    // cp.async staging: warp w stages batch row (b0+w), 4KB coalesced
    auto stage = [&](int t, float* buf) {
        const float* src = g_gx + ((size_t)(b0 + w) * TT + t) * GG;
        uint32_t dst = (uint32_t)__cvta_generic_to_shared(buf + w * GXR);
#pragma unroll
        for (int i = 0; i < 8; i++) {
            asm volatile("cp.async.cg.shared.global [%0], [%1], 16;"
                         :: "r"(dst + i * 512 + lane * 16),
                            "l"(src + i * 128 + lane * 4) : "memory");
        }
    };

    stage(0, gxb[0]);
    asm volatile("cp.async.commit_group;" ::: "memory");

    for (int t = 0; t < TT; t++) {
        float* gxc = gxb[t % 3];

        if (t + 1 < TT) {
            stage(t + 1, gxb[(t + 1) % 3]);
            asm volatile("cp.async.commit_group;" ::: "memory");
            asm volatile("cp.async.wait_group 1;" ::: "memory");
        } else {
            asm volatile("cp.async.wait_group 0;" ::: "memory");
        }
        __syncthreads();   // stage(t) visible; shA writes of step t-1 visible

        const uint32_t* shR = shA + (t & 1) * 2048;          // read h(t-1)
        __half* shW = shA_h + ((t + 1) & 1) * 4096;          // write h(t) [FIXED stride]

        // ---- acc = gx fragments (from smem) ----
        float acc[8][4];
        {
            const float* rl = gxc + g * GXR + w * 64 + cq * 2;
            const float* rh = gxc + (g + 8) * GXR + w * 64 + cq * 2;
#pragma unroll
            for (int ni = 0; ni < 8; ni++) {
                float2 lo = *(const float2*)(rl + ni * 8);
                float2 hi = *(const float2*)(rh + ni * 8);
                acc[ni][0] = lo.x; acc[ni][1] = lo.y;
                acc[ni][2] = hi.x; acc[ni][3] = hi.y;
            }
        }

        // ---- mma over 16 kblks (K=16 each), W ring-3 register prefetch ----
        uint4 wb[3][4];
#pragma unroll
        for (int p = 0; p < 4; p++) wb[0][p] = Wp[(size_t)(((0 * 16 + w) * 4 + p) * 32) + lane];
#pragma unroll
        for (int p = 0; p < 4; p++) wb[1][p] = Wp[(size_t)(((1 * 16 + w) * 4 + p) * 32) + lane];

#pragma unroll
        for (int kb = 0; kb < 16; kb++) {
            if (kb + 2 < 16) {
#pragma unroll
                for (int p = 0; p < 4; p++)
                    wb[(kb + 2) % 3][p] = Wp[(size_t)((((kb + 2) * 16 + w) * 4 + p) * 32) + lane];
            }
            uint4 av = *(const uint4*)&shR[(kb * 32 + lane) * 4];
            uint32_t a[4] = {av.x, av.y, av.z, av.w};
            const uint4* wc = wb[kb % 3];
#pragma unroll
            for (int p = 0; p < 4; p++) {
                mma_f16(acc[2 * p],     a, wc[p].x, wc[p].y);
                mma_f16(acc[2 * p + 1], a, wc[p].z, wc[p].w);
            }
        }

        // ---- fused update: shfl regroups gates; even lane row g, odd row g+8 ----
#pragma unroll
        for (int ni = 0; ni < 8; ni++) {
            float sx = pr ? acc[ni][0] : acc[ni][2];
            float sy = pr ? acc[ni][1] : acc[ni][3];
            float rx = __shfl_xor_sync(0xffffffffu, sx, 1);
            float ry = __shfl_xor_sync(0xffffffffu, sy, 1);
            float gi = pr ? rx : acc[ni][0];
            float gf = pr ? ry : acc[ni][1];
            float gc = pr ? acc[ni][2] : rx;
            float go = pr ? acc[ni][3] : ry;

            float ig = sigmoid_fast(gi);
            float fg = sigmoid_fast(gf);
            float gv = tanh_fast(gc);
            float og = sigmoid_fast(go);
            float cn = fg * cst[ni] + ig * gv;
            cst[ni] = cn;
            float h = og * tanh_fast(cn);

            out[outBase0 + (size_t)t * HH + ni * 2] = h;

            // fp16 A-fragment store into write buffer:
            // kblk = w, laneA = (g<<2)|(ni&3), word = ((ni>>2)<<1)|pr, half = hf
            int laneA = (g << 2) | (ni & 3);
            int word  = ((ni >> 2) << 1) | pr;
            shW[(((w * 32 + laneA) << 2) + word) * 2 + hf] = __float2half_rn(h);
        }
        // single barrier per step (top of loop) covers shA write->read and
        // gx buffer recycle (3 buffers tolerate 1-epoch warp skew).
    }
}

// ---------------------------------------------------------------------------
// Launch
// ---------------------------------------------------------------------------
extern "C" void kernel_launch(void* const* d_in, const int* in_sizes, int n_in,
                              void* d_out, int out_size)
{
    const float* x     = (const float*)d_in[0];
    const float* W_ih1 = (const float*)d_in[1];
    const float* W_hh1 = (const float*)d_in[2];
    const float* b_ih1 = (const float*)d_in[3];
    const float* b_hh1 = (const float*)d_in[4];
    const float* W_ih2 = (const float*)d_in[5];
    const float* W_hh2 = (const float*)d_in[6];
    const float* b_ih2 = (const float*)d_in[7];
    const float* b_hh2 = (const float*)d_in[8];
    float* out = (float*)d_out;

    const int scan_smem = 48 * GXR * 4 + 2 * 2048 * 4;   // 198,144 + 16,384 = 214,528 B
    cudaFuncSetAttribute(lstm_scan5,
                         cudaFuncAttributeMaxDynamicSharedMemorySize, scan_smem);

    dim3 ggrid(BT / 128, GG / 64);  // 672 x 16

    // Layer 1
    prep_weights<<<1024, 256>>>(W_ih1, W_hh1, b_ih1, b_hh1, II);
    gemm_gx_tf32<II><<<ggrid, 256>>>(x);
    lstm_scan5<<<BB / 16, 512, scan_smem>>>(nullptr);      // writes g_out1

    // Layer 2
    prep_weights<<<1024, 256>>>(W_ih2, W_hh2, b_ih2, b_hh2, HH);
    gemm_gx_tf32<HH><<<ggrid, 256>>>(nullptr);
    lstm_scan5<<<BB / 16, 512, scan_smem>>>(out);           // writes final output
}

// round 10
// speedup vs baseline: 1.2829x; 1.2829x over previous
#include <cuda_runtime.h>
#include <cuda_fp16.h>
#include <math.h>
#include <stdint.h>

// Problem constants
#define BB 512
#define TT 168
#define II 64
#define HH 256
#define GG 1024   // 4*H
#define BT (BB*TT)
#define GXR 1032  // staged gx / gates smem row stride (floats)

// ---------------------------------------------------------------------------
// Scratch (device globals: allocation-free rule)
// ---------------------------------------------------------------------------
__device__ float g_gx[(size_t)BT * GG];   // gate pre-activations, interleaved gate layout
__device__ float g_out1[(size_t)BT * HH]; // layer-1 hidden outputs
__device__ float g_WT[HH * GG];           // W_ih transposed+interleaved (GEMM B)
__device__ __half g_WhhPh[HH * GG];       // W_hh fp16, scan A-fragment layout (see prep)
__device__ float g_bias[GG];              // b_ih+b_hh, interleaved

// Interleaving: column n = j*4+q maps to raw gate row r = q*256 + j
// (q: 0=i, 1=f, 2=g, 3=o).

// ---------------------------------------------------------------------------
// tf32 / fp16 mma / activation helpers
// ---------------------------------------------------------------------------
__device__ __forceinline__ uint32_t f2tf32(float x) {
    uint32_t r;
    asm("cvt.rna.tf32.f32 %0, %1;" : "=r"(r) : "f"(x));
    return r;
}

__device__ __forceinline__ void mma_tf32(float* c, const uint32_t* a, uint32_t b0, uint32_t b1) {
    asm volatile(
        "mma.sync.aligned.m16n8k8.row.col.f32.tf32.tf32.f32 "
        "{%0,%1,%2,%3}, {%4,%5,%6,%7}, {%8,%9}, {%0,%1,%2,%3};"
        : "+f"(c[0]), "+f"(c[1]), "+f"(c[2]), "+f"(c[3])
        : "r"(a[0]), "r"(a[1]), "r"(a[2]), "r"(a[3]), "r"(b0), "r"(b1));
}

// m16n8k16 fp16 inputs, fp32 accumulate
__device__ __forceinline__ void mma_f16(float* c, const uint32_t* a, uint32_t b0, uint32_t b1) {
    asm volatile(
        "mma.sync.aligned.m16n8k16.row.col.f32.f16.f16.f32 "
        "{%0,%1,%2,%3}, {%4,%5,%6,%7}, {%8,%9}, {%0,%1,%2,%3};"
        : "+f"(c[0]), "+f"(c[1]), "+f"(c[2]), "+f"(c[3])
        : "r"(a[0]), "r"(a[1]), "r"(a[2]), "r"(a[3]), "r"(b0), "r"(b1));
}

__device__ __forceinline__ float sigmoid_fast(float x) {
    return __fdividef(1.f, 1.f + __expf(-x));
}
__device__ __forceinline__ float tanh_fast(float x) {
    float xc = fminf(fmaxf(x, -15.f), 15.f);
    float e = __expf(-2.f * xc);
    return __fdividef(1.f - e, 1.f + e);
}

// ---------------------------------------------------------------------------
// Weight prep: transpose + gate-interleave + bias combine + scan W permute.
// Scan W fp16 layout = m16n8k16 **A fragments** (gates = M, k = K):
//   warp w of 16 owns gates [w*64, w*64+64) = 4 m16-blocks (mblk 0..3).
//   For gate column n (interleaved) and k:
//     m = n&15, gA = m&7, rlo = m>>3; kin = k&15, cA = (kin&7)>>1,
//     khi = kin>>3, hf = kin&1; reg ridx = rlo + 2*khi; lane = (gA<<2)|cA.
//   uint4 index = ((kblk*16 + w)*4 + mblk)*32 + lane   (1 LDG.128 = 1 A-frag)
// ---------------------------------------------------------------------------
__global__ void prep_weights(const float* __restrict__ W_ih,
                             const float* __restrict__ W_hh,
                             const float* __restrict__ b_ih,
                             const float* __restrict__ b_hh,
                             int K)
{
    int idx = blockIdx.x * 256 + threadIdx.x;  // 0 .. 256*1024-1
    int n = idx & (GG - 1);
    int k = idx >> 10;
    int j = n >> 2;
    int q = n & 3;
    int r = q * HH + j;
    if (k < K) g_WT[k * GG + n] = W_ih[r * K + k];

    {
        float wv = W_hh[r * HH + k];
        int w = n >> 6;
        int mblk = (n >> 4) & 3;
        int m = n & 15;
        int gA = m & 7, rlo = m >> 3;
        int kblk = k >> 4, kin = k & 15;
        int cA = (kin & 7) >> 1, khi = kin >> 3, hf = kin & 1;
        int ridx = rlo + 2 * khi;
        int laneA = (gA << 2) | cA;
        size_t o = (((((size_t)(kblk * 16 + w) * 4 + mblk) * 32 + laneA) * 4)
                    + ridx) * 2 + hf;
        g_WhhPh[o] = __float2half_rn(wv);
    }
    if (k == 0) g_bias[n] = b_ih[r] + b_hh[r];
}

// ---------------------------------------------------------------------------
// Feed-forward GEMM (tensor cores, tf32): unchanged (validated R2-R9).
// ---------------------------------------------------------------------------
template <int K>
__global__ __launch_bounds__(256)
void gemm_gx_tf32(const float* __restrict__ X_in)
{
    const float* X = X_in ? X_in : (const float*)g_out1;
    constexpr int KT = K / 32;

    __shared__ uint32_t sA[2][4096];
    __shared__ uint32_t sB[2][2048];

    const int tid  = threadIdx.x;
    const int warp = tid >> 5;
    const int lane = tid & 31;
    const int m0 = blockIdx.x * 128;
    const int n0 = blockIdx.y * 64;
    const int wmb = (warp >> 1) * 2;
    const int wnb = (warp & 1) * 4;

    float acc[2][4][4];
#pragma unroll
    for (int i = 0; i < 2; i++)
#pragma unroll
        for (int j = 0; j < 4; j++)
#pragma unroll
            for (int q = 0; q < 4; q++) acc[i][j][q] = 0.f;

    float4 av[4];
    float4 bv[2];

    auto ldg_tile = [&](int kt) {
#pragma unroll
        for (int i = 0; i < 4; i++) {
            int v = tid + 256 * i;
            int row = v >> 3;
            int kc = (v & 7) * 4;
            av[i] = *(const float4*)(X + (size_t)(m0 + row) * K + kt * 32 + kc);
        }
#pragma unroll
        for (int i = 0; i < 2; i++) {
            int v = tid + 256 * i;
            int row = v >> 4;
            int nc = (v & 15) * 4;
            bv[i] = *(const float4*)(g_WT + (size_t)(kt * 32 + row) * GG + n0 + nc);
        }
    };

    auto sts_tile = [&](int buf) {
#pragma unroll
        for (int i = 0; i < 4; i++) {
            int v = tid + 256 * i;
            int row = v >> 3;
            int kc0 = (v & 7) * 4;
            int mblk = row >> 4, mr = row & 15;
            float f[4] = {av[i].x, av[i].y, av[i].z, av[i].w};
#pragma unroll
            for (int j = 0; j < 4; j++) {
                int kc = kc0 + j;
                int kblk = kc >> 3, kin = kc & 7;
                int t = ((mr & 7) << 2) | (kin & 3);
                int slot = ((kin >> 2) << 1) | (mr >> 3);
                sA[buf][(((kblk << 3) | mblk) << 7) + (t << 2) + slot] = f2tf32(f[j]);
            }
        }
#pragma unroll
        for (int i = 0; i < 2; i++) {
            int v = tid + 256 * i;
            int row = v >> 4;
            int nc0 = (v & 15) * 4;
            int kblk = row >> 3, kin = row & 7;
            float f[4] = {bv[i].x, bv[i].y, bv[i].z, bv[i].w};
#pragma unroll
            for (int j = 0; j < 4; j++) {
                int nc = nc0 + j;
                int nblk = nc >> 3, nin = nc & 7;
                int t = (nin << 2) | (kin & 3);
                int slot = kin >> 2;
                sB[buf][(((kblk << 3) | nblk) << 6) + (t << 1) + slot] = f2tf32(f[j]);
            }
        }
    };

    auto compute = [&](int buf) {
#pragma unroll
        for (int ks = 0; ks < 4; ks++) {
            uint32_t afr[2][4];
            uint32_t bfr[4][2];
#pragma unroll
            for (int mi = 0; mi < 2; mi++) {
                uint4 a = *(const uint4*)&sA[buf][(((ks << 3) | (wmb + mi)) << 7) + (lane << 2)];
                afr[mi][0] = a.x; afr[mi][1] = a.y; afr[mi][2] = a.z; afr[mi][3] = a.w;
            }
#pragma unroll
            for (int ni = 0; ni < 4; ni++) {
                uint2 b = *(const uint2*)&sB[buf][(((ks << 3) | (wnb + ni)) << 6) + (lane << 1)];
                bfr[ni][0] = b.x; bfr[ni][1] = b.y;
            }
#pragma unroll
            for (int mi = 0; mi < 2; mi++)
#pragma unroll
                for (int ni = 0; ni < 4; ni++)
                    mma_tf32(acc[mi][ni], afr[mi], bfr[ni][0], bfr[ni][1]);
        }
    };

    ldg_tile(0);
    sts_tile(0);
    __syncthreads();
#pragma unroll
    for (int kt = 0; kt < KT; kt++) {
        if (kt + 1 < KT) ldg_tile(kt + 1);
        compute(kt & 1);
        if (kt + 1 < KT) sts_tile((kt + 1) & 1);
        __syncthreads();
    }

    const int g = lane >> 2;
    const int cq = lane & 3;
#pragma unroll
    for (int ni = 0; ni < 4; ni++) {
        int gn = n0 + ((wnb + ni) << 3) + cq * 2;
        float bx = g_bias[gn];
        float by = g_bias[gn + 1];
#pragma unroll
        for (int mi = 0; mi < 2; mi++) {
            int gm = m0 + ((wmb + mi) << 4) + g;
            float2 r0 = make_float2(acc[mi][ni][0] + bx, acc[mi][ni][1] + by);
            float2 r1 = make_float2(acc[mi][ni][2] + bx, acc[mi][ni][3] + by);
            *(float2*)(g_gx + (size_t)gm * GG + gn) = r0;
            *(float2*)(g_gx + (size_t)(gm + 8) * GG + gn) = r1;
        }
    }
}

// ---------------------------------------------------------------------------
// Recurrent scan v6 (operand-swapped fp16 HMMA): 64 CTAs x MB=8 rows,
// 512 threads (16 warps). D[m=16 gates, n=8 batch] = A(W) x B(h):
//   A = W_hh fragments streamed from L2 (ring-3 register prefetch, same
//       512KB/step, 64 LDG.128/warp), B = h fragments from 4KB smem.
// HMMA per warp HALVED vs v4 (64 vs 128) -> per-SM mma.sync floor halved.
// Warp w owns gates [w*64, w*64+64) (4 m16-blocks). Two syncs per step:
// gates (fp32) staged via smem [batch][gate] for the R7-proven update phase.
// ---------------------------------------------------------------------------
__global__ __launch_bounds__(512, 1)
void lstm_scan6(float* __restrict__ out_in)
{
    float* out = out_in ? out_in : (float*)g_out1;

    extern __shared__ float smem_f[];
    float* gxb[3] = { smem_f, smem_f + 8 * GXR, smem_f + 16 * GXR };  // 3x [8][GXR]
    float* gates  = smem_f + 24 * GXR;                                 // [8][GXR]
    uint32_t* shB = (uint32_t*)(gates + 8 * GXR);   // 2 x 1024 u32: [kblk16][lane32][2]
    __half* shB_h = (__half*)shB;

    const int tid  = threadIdx.x;
    const int w    = tid >> 5;
    const int lane = tid & 31;
    const int g    = lane >> 2;       // D gate row (and +8)
    const int c2   = lane & 3;        // D batch col pair base (2*c2, 2*c2+1)
    const int b0   = blockIdx.x * 8;

    // update-phase constants: thread owns h column j, rows [rg*4, rg*4+4)
    const int j  = tid & 255;
    const int rg = tid >> 8;
    const int kblkU = j >> 4, kinU = j & 15;
    const int cU    = (kinU & 7) >> 1;
    const int hfU   = kinU & 1;
    const int ridxU = kinU >> 3;

    for (int i = tid; i < 2048; i += 512) shB[i] = 0u;
    float cst[4] = {0.f, 0.f, 0.f, 0.f};
    __syncthreads();

    const uint4* __restrict__ Wp = (const uint4*)g_WhhPh;

    // cp.async staging: warp w stages half of batch row (w>>1), 2KB coalesced
    auto stage = [&](int t, float* buf) {
        int row = w >> 1;
        int half = (w & 1) * 512;   // float offset
        const float* src = g_gx + ((size_t)(b0 + row) * TT + t) * GG + half;
        uint32_t dst = (uint32_t)__cvta_generic_to_shared(buf + row * GXR + half);
#pragma unroll
        for (int i = 0; i < 4; i++) {
            asm volatile("cp.async.cg.shared.global [%0], [%1], 16;"
                         :: "r"(dst + i * 512 + lane * 16),
                            "l"(src + i * 128 + lane * 4) : "memory");
        }
    };

    stage(0, gxb[0]);
    asm volatile("cp.async.commit_group;" ::: "memory");

    for (int t = 0; t < TT; t++) {
        float* gxc = gxb[t % 3];

        if (t + 1 < TT) {
            stage(t + 1, gxb[(t + 1) % 3]);
            asm volatile("cp.async.commit_group;" ::: "memory");
            asm volatile("cp.async.wait_group 1;" ::: "memory");
        } else {
            asm volatile("cp.async.wait_group 0;" ::: "memory");
        }
        __syncthreads();   // gx(t) staged; shB writes of step t-1 visible; gates free

        const uint32_t* shR = shB + (t & 1) * 1024;          // read h(t-1) B-frags
        __half* shW = shB_h + ((t + 1) & 1) * 2048;          // write h(t)

        // ---- mma: acc[mblk] = W(A) x h(B), 16 kblks, W ring-3 prefetch ----
        float acc[4][4];
#pragma unroll
        for (int mb = 0; mb < 4; mb++)
#pragma unroll
            for (int q = 0; q < 4; q++) acc[mb][q] = 0.f;

        uint4 wb[3][4];
#pragma unroll
        for (int p = 0; p < 4; p++) wb[0][p] = Wp[(size_t)(((0 * 16 + w) * 4 + p) * 32) + lane];
#pragma unroll
        for (int p = 0; p < 4; p++) wb[1][p] = Wp[(size_t)(((1 * 16 + w) * 4 + p) * 32) + lane];

#pragma unroll
        for (int kb = 0; kb < 16; kb++) {
            if (kb + 2 < 16) {
#pragma unroll
                for (int p = 0; p < 4; p++)
                    wb[(kb + 2) % 3][p] = Wp[(size_t)((((kb + 2) * 16 + w) * 4 + p) * 32) + lane];
            }
            uint2 bv = *(const uint2*)&shR[(kb * 32 + lane) * 2];
            const uint4* wc = wb[kb % 3];
#pragma unroll
            for (int mb = 0; mb < 4; mb++) {
                uint32_t a[4] = {wc[mb].x, wc[mb].y, wc[mb].z, wc[mb].w};
                mma_f16(acc[mb], a, bv.x, bv.y);
            }
        }

        // ---- gates -> smem [batch][gate]: c0,c1 = gate g, batch 2c2/2c2+1 ----
#pragma unroll
        for (int mb = 0; mb < 4; mb++) {
            int gg = w * 64 + mb * 16 + g;
            gates[(2 * c2) * GXR + gg]         = acc[mb][0];
            gates[(2 * c2 + 1) * GXR + gg]     = acc[mb][1];
            gates[(2 * c2) * GXR + gg + 8]     = acc[mb][2];
            gates[(2 * c2 + 1) * GXR + gg + 8] = acc[mb][3];
        }
        __syncthreads();

        // ---- elementwise LSTM update: thread = col j, 4 rows ----
#pragma unroll
        for (int i = 0; i < 4; i++) {
            int m = rg * 4 + i;
            float4 gx4 = *(const float4*)(gxc + m * GXR + j * 4);
            float4 gt  = *(const float4*)(gates + m * GXR + j * 4);
            float ig = sigmoid_fast(gt.x + gx4.x);
            float fg = sigmoid_fast(gt.y + gx4.y);
            float gv = tanh_fast(gt.z + gx4.z);
            float og = sigmoid_fast(gt.w + gx4.w);
            float cn = fg * cst[i] + ig * gv;
            cst[i] = cn;
            float h = og * tanh_fast(cn);

            out[((size_t)(b0 + m) * TT + t) * HH + j] = h;

            // h -> fp16 B-fragment (k = j, n = m): lane = m*4+cU, reg ridxU, half hfU
            int laneB = m * 4 + cU;
            shW[(((kblkU * 32 + laneB) * 2) + ridxU) * 2 + hfU] = __float2half_rn(h);
        }
        // next iteration's top barrier covers shB write->read and gates reuse.
    }
}

// ---------------------------------------------------------------------------
// Launch
// ---------------------------------------------------------------------------
extern "C" void kernel_launch(void* const* d_in, const int* in_sizes, int n_in,
                              void* d_out, int out_size)
{
    const float* x     = (const float*)d_in[0];
    const float* W_ih1 = (const float*)d_in[1];
    const float* W_hh1 = (const float*)d_in[2];
    const float* b_ih1 = (const float*)d_in[3];
    const float* b_hh1 = (const float*)d_in[4];
    const float* W_ih2 = (const float*)d_in[5];
    const float* W_hh2 = (const float*)d_in[6];
    const float* b_ih2 = (const float*)d_in[7];
    const float* b_hh2 = (const float*)d_in[8];
    float* out = (float*)d_out;

    const int scan_smem = 32 * GXR * 4 + 2 * 1024 * 4;   // 132,096 + 8,192 = 140,288 B
    cudaFuncSetAttribute(lstm_scan6,
                         cudaFuncAttributeMaxDynamicSharedMemorySize, scan_smem);

    dim3 ggrid(BT / 128, GG / 64);  // 672 x 16

    // Layer 1
    prep_weights<<<1024, 256>>>(W_ih1, W_hh1, b_ih1, b_hh1, II);
    gemm_gx_tf32<II><<<ggrid, 256>>>(x);
    lstm_scan6<<<BB / 8, 512, scan_smem>>>(nullptr);       // 64 CTAs, writes g_out1

    // Layer 2
    prep_weights<<<1024, 256>>>(W_ih2, W_hh2, b_ih2, b_hh2, HH);
    gemm_gx_tf32<HH><<<ggrid, 256>>>(nullptr);
    lstm_scan6<<<BB / 8, 512, scan_smem>>>(out);            // writes final output
}

// round 11
// speedup vs baseline: 1.5671x; 1.2216x over previous
#include <cuda_runtime.h>
#include <cuda_fp16.h>
#include <math.h>
#include <stdint.h>

// Problem constants
#define BB 512
#define TT 168
#define II 64
#define HH 256
#define GG 1024   // 4*H
#define BT (BB*TT)
#define GXS 260   // staged gx / gates smem row stride (floats), conflict-free

// ---------------------------------------------------------------------------
// Scratch (device globals: allocation-free rule)
// ---------------------------------------------------------------------------
__device__ float g_gx[(size_t)BT * GG];   // gate pre-activations, interleaved gate layout
__device__ float g_out1[(size_t)BT * HH]; // layer-1 hidden outputs
__device__ float g_WT[HH * GG];           // W_ih transposed+interleaved (GEMM B)
__device__ __half g_WhhPh[HH * GG];       // W_hh fp16, per-rank A-fragment layout (see prep)
__device__ float g_bias[GG];              // b_ih+b_hh, interleaved

// Interleaving: column n = j*4+q maps to raw gate row r = q*256 + j
// (q: 0=i, 1=f, 2=g, 3=o).

// ---------------------------------------------------------------------------
// tf32 / fp16 mma / activation helpers
// ---------------------------------------------------------------------------
__device__ __forceinline__ uint32_t f2tf32(float x) {
    uint32_t r;
    asm("cvt.rna.tf32.f32 %0, %1;" : "=r"(r) : "f"(x));
    return r;
}

__device__ __forceinline__ void mma_tf32(float* c, const uint32_t* a, uint32_t b0, uint32_t b1) {
    asm volatile(
        "mma.sync.aligned.m16n8k8.row.col.f32.tf32.tf32.f32 "
        "{%0,%1,%2,%3}, {%4,%5,%6,%7}, {%8,%9}, {%0,%1,%2,%3};"
        : "+f"(c[0]), "+f"(c[1]), "+f"(c[2]), "+f"(c[3])
        : "r"(a[0]), "r"(a[1]), "r"(a[2]), "r"(a[3]), "r"(b0), "r"(b1));
}

// m16n8k16 fp16 inputs, fp32 accumulate
__device__ __forceinline__ void mma_f16(float* c, const uint32_t* a, uint32_t b0, uint32_t b1) {
    asm volatile(
        "mma.sync.aligned.m16n8k16.row.col.f32.f16.f16.f32 "
        "{%0,%1,%2,%3}, {%4,%5,%6,%7}, {%8,%9}, {%0,%1,%2,%3};"
        : "+f"(c[0]), "+f"(c[1]), "+f"(c[2]), "+f"(c[3])
        : "r"(a[0]), "r"(a[1]), "r"(a[2]), "r"(a[3]), "r"(b0), "r"(b1));
}

__device__ __forceinline__ float sigmoid_fast(float x) {
    return __fdividef(1.f, 1.f + __expf(-x));
}
__device__ __forceinline__ float tanh_fast(float x) {
    float xc = fminf(fmaxf(x, -15.f), 15.f);
    float e = __expf(-2.f * xc);
    return __fdividef(1.f - e, 1.f + e);
}

// ---------------------------------------------------------------------------
// Weight prep: transpose + gate-interleave + bias combine + scan W permute.
// Scan W fp16 layout = m16n8k16 A fragments (gates = M, k = K), sliced for
// a 4-CTA cluster: rank = n>>8 owns gate slice [rank*256, rank*256+256);
// within a slice, warp ws = (n>>4)&15 owns one m16 block.
//   m = n&15: gA = m&7, rlo = m>>3; kin = k&15: cA = (kin&7)>>1, khi = kin>>3,
//   hf = kin&1; ridx = rlo + 2*khi; laneA = (gA<<2)|cA.
//   uint4 index = ((rank*16 + kblk)*16 + ws)*32 + laneA   (kblk = k>>4)
// -> each rank's slice is a contiguous 8192 uint4 (128KB) block.
// ---------------------------------------------------------------------------
__global__ void prep_weights(const float* __restrict__ W_ih,
                             const float* __restrict__ W_hh,
                             const float* __restrict__ b_ih,
                             const float* __restrict__ b_hh,
                             int K)
{
    int idx = blockIdx.x * 256 + threadIdx.x;  // 0 .. 256*1024-1
    int n = idx & (GG - 1);
    int k = idx >> 10;
    int j = n >> 2;
    int q = n & 3;
    int r = q * HH + j;
    if (k < K) g_WT[k * GG + n] = W_ih[r * K + k];

    {
        float wv = W_hh[r * HH + k];
        int rank = n >> 8;
        int ws   = (n >> 4) & 15;
        int m    = n & 15;
        int gA = m & 7, rlo = m >> 3;
        int kblk = k >> 4, kin = k & 15;
        int cA = (kin & 7) >> 1, khi = kin >> 3, hf = kin & 1;
        int ridx = rlo + 2 * khi;
        int laneA = (gA << 2) | cA;
        size_t u4 = ((size_t)(rank * 16 + kblk) * 16 + ws) * 32 + laneA;
        g_WhhPh[(u4 * 4 + ridx) * 2 + hf] = __float2half_rn(wv);
    }
    if (k == 0) g_bias[n] = b_ih[r] + b_hh[r];
}

// ---------------------------------------------------------------------------
// Feed-forward GEMM (tensor cores, tf32): unchanged (validated R2-R10).
// ---------------------------------------------------------------------------
template <int K>
__global__ __launch_bounds__(256)
void gemm_gx_tf32(const float* __restrict__ X_in)
{
    const float* X = X_in ? X_in : (const float*)g_out1;
    constexpr int KT = K / 32;

    __shared__ uint32_t sA[2][4096];
    __shared__ uint32_t sB[2][2048];

    const int tid  = threadIdx.x;
    const int warp = tid >> 5;
    const int lane = tid & 31;
    const int m0 = blockIdx.x * 128;
    const int n0 = blockIdx.y * 64;
    const int wmb = (warp >> 1) * 2;
    const int wnb = (warp & 1) * 4;

    float acc[2][4][4];
#pragma unroll
    for (int i = 0; i < 2; i++)
#pragma unroll
        for (int j = 0; j < 4; j++)
#pragma unroll
            for (int q = 0; q < 4; q++) acc[i][j][q] = 0.f;

    float4 av[4];
    float4 bv[2];

    auto ldg_tile = [&](int kt) {
#pragma unroll
        for (int i = 0; i < 4; i++) {
            int v = tid + 256 * i;
            int row = v >> 3;
            int kc = (v & 7) * 4;
            av[i] = *(const float4*)(X + (size_t)(m0 + row) * K + kt * 32 + kc);
        }
#pragma unroll
        for (int i = 0; i < 2; i++) {
            int v = tid + 256 * i;
            int row = v >> 4;
            int nc = (v & 15) * 4;
            bv[i] = *(const float4*)(g_WT + (size_t)(kt * 32 + row) * GG + n0 + nc);
        }
    };

    auto sts_tile = [&](int buf) {
#pragma unroll
        for (int i = 0; i < 4; i++) {
            int v = tid + 256 * i;
            int row = v >> 3;
            int kc0 = (v & 7) * 4;
            int mblk = row >> 4, mr = row & 15;
            float f[4] = {av[i].x, av[i].y, av[i].z, av[i].w};
#pragma unroll
            for (int j = 0; j < 4; j++) {
                int kc = kc0 + j;
                int kblk = kc >> 3, kin = kc & 7;
                int t = ((mr & 7) << 2) | (kin & 3);
                int slot = ((kin >> 2) << 1) | (mr >> 3);
                sA[buf][(((kblk << 3) | mblk) << 7) + (t << 2) + slot] = f2tf32(f[j]);
            }
        }
#pragma unroll
        for (int i = 0; i < 2; i++) {
            int v = tid + 256 * i;
            int row = v >> 4;
            int nc0 = (v & 15) * 4;
            int kblk = row >> 3, kin = row & 7;
            float f[4] = {bv[i].x, bv[i].y, bv[i].z, bv[i].w};
#pragma unroll
            for (int j = 0; j < 4; j++) {
                int nc = nc0 + j;
                int nblk = nc >> 3, nin = nc & 7;
                int t = (nin << 2) | (kin & 3);
                int slot = kin >> 2;
                sB[buf][(((kblk << 3) | nblk) << 6) + (t << 1) + slot] = f2tf32(f[j]);
            }
        }
    };

    auto compute = [&](int buf) {
#pragma unroll
        for (int ks = 0; ks < 4; ks++) {
            uint32_t afr[2][4];
            uint32_t bfr[4][2];
#pragma unroll
            for (int mi = 0; mi < 2; mi++) {
                uint4 a = *(const uint4*)&sA[buf][(((ks << 3) | (wmb + mi)) << 7) + (lane << 2)];
                afr[mi][0] = a.x; afr[mi][1] = a.y; afr[mi][2] = a.z; afr[mi][3] = a.w;
            }
#pragma unroll
            for (int ni = 0; ni < 4; ni++) {
                uint2 b = *(const uint2*)&sB[buf][(((ks << 3) | (wnb + ni)) << 6) + (lane << 1)];
                bfr[ni][0] = b.x; bfr[ni][1] = b.y;
            }
#pragma unroll
            for (int mi = 0; mi < 2; mi++)
#pragma unroll
                for (int ni = 0; ni < 4; ni++)
                    mma_tf32(acc[mi][ni], afr[mi], bfr[ni][0], bfr[ni][1]);
        }
    };

    ldg_tile(0);
    sts_tile(0);
    __syncthreads();
#pragma unroll
    for (int kt = 0; kt < KT; kt++) {
        if (kt + 1 < KT) ldg_tile(kt + 1);
        compute(kt & 1);
        if (kt + 1 < KT) sts_tile((kt + 1) & 1);
        __syncthreads();
    }

    const int g = lane >> 2;
    const int cq = lane & 3;
#pragma unroll
    for (int ni = 0; ni < 4; ni++) {
        int gn = n0 + ((wnb + ni) << 3) + cq * 2;
        float bx = g_bias[gn];
        float by = g_bias[gn + 1];
#pragma unroll
        for (int mi = 0; mi < 2; mi++) {
            int gm = m0 + ((wmb + mi) << 4) + g;
            float2 r0 = make_float2(acc[mi][ni][0] + bx, acc[mi][ni][1] + by);
            float2 r1 = make_float2(acc[mi][ni][2] + bx, acc[mi][ni][3] + by);
            *(float2*)(g_gx + (size_t)gm * GG + gn) = r0;
            *(float2*)(g_gx + (size_t)(gm + 8) * GG + gn) = r1;
        }
    }
}

// ---------------------------------------------------------------------------
// Recurrent scan v7: 4-CTA cluster, SMEM-RESIDENT W (zero W traffic/step).
// 32 clusters x 4 CTAs = 128 CTAs; cluster owns MB=16 batch rows; CTA rank r
// owns gate slice [r*256, r*256+256) == h columns [r*64, (r+1)*64).
// Per step per CTA (512 threads, 16 warps; warp w owns m16 gate block w):
//   D[m=16 gates, n=16 batch] = A(W from SMEM) x B(h frags, full k=256)
//   = 2 n8-blocks x 16 kblks = 32 HMMA/warp (half of R10).
// h exchange: each thread writes its updated h values (fp16 B-fragments)
// directly into all 4 CTAs' shB write buffer via st.shared::cluster.u16;
// its own barrier.cluster.arrive releases them; consumers' wait acquires.
// ONE cluster barrier pair + TWO __syncthreads per step. shB double-buffered;
// gx cp.async triple-buffered (slice of 256 floats/row).
// ---------------------------------------------------------------------------
__global__ __launch_bounds__(512, 1) __cluster_dims__(4, 1, 1)
void lstm_scan7(float* __restrict__ out_in)
{
    float* out = out_in ? out_in : (float*)g_out1;

    extern __shared__ float smem_f[];
    uint32_t* sW  = (uint32_t*)smem_f;        // 32768 u32 = 128KB W slice (A-frags)
    uint32_t* shB = sW + 32768;               // 2 x 2048 u32 h B-frags: [kblk16][n8b2][lane32][2]
    float* gx0   = (float*)(shB + 4096);
    float* gxb[3] = { gx0, gx0 + 16 * GXS, gx0 + 32 * GXS };   // 3 x [16][GXS]
    float* gates = gx0 + 48 * GXS;            // [16][GXS] (slice cols 0..255)

    const int tid  = threadIdx.x;
    const int w    = tid >> 5;
    const int lane = tid & 31;
    const int g    = lane >> 2;
    const int c2   = lane & 3;

    uint32_t rank;
    asm("mov.u32 %0, %%cluster_ctarank;" : "=r"(rank));
    const int b0 = (blockIdx.x >> 2) * 16;

    // ---- one-time: W slice -> smem; zero h frag buffers ----
    {
        const uint4* Wg = ((const uint4*)g_WhhPh) + (size_t)rank * 8192;
        uint4* sW4 = (uint4*)sW;
        for (int i = tid; i < 8192; i += 512) sW4[i] = Wg[i];
        for (int i = tid; i < 4096; i += 512) shB[i] = 0u;
    }

    // ---- update-phase constants: thread owns h col jg, rows {rg*2, rg*2+1} ----
    const int jl = tid & 63;
    const int rg = tid >> 6;
    const int jg = (int)rank * 64 + jl;
    const int kblkU = jg >> 4, kinU = jg & 15;
    const int cU = (kinU & 7) >> 1, hfU = kinU & 1, ridxU = kinU >> 3;
    float cst[2] = {0.f, 0.f};

    // ---- peer shB base addresses (dsmem) ----
    uint32_t shB_local;
    asm("{ .reg .u64 t; cvta.to.shared.u64 t, %1; cvt.u32.u64 %0, t; }"
        : "=r"(shB_local) : "l"((void*)shB));
    uint32_t peerB[4];
#pragma unroll
    for (int d = 0; d < 4; d++)
        asm("mapa.shared::cluster.u32 %0, %1, %2;" : "=r"(peerB[d]) : "r"(shB_local), "r"(d));

    // cp.async: warp w stages row (b0+w)'s 256-float gate slice (1KB)
    auto stage = [&](int t, float* buf) {
        const float* src = g_gx + ((size_t)(b0 + w) * TT + t) * GG + rank * 256;
        uint32_t dst = (uint32_t)__cvta_generic_to_shared(buf + w * GXS);
#pragma unroll
        for (int i = 0; i < 2; i++)
            asm volatile("cp.async.cg.shared.global [%0], [%1], 16;"
                         :: "r"(dst + i * 512 + lane * 16),
                            "l"(src + i * 128 + lane * 4) : "memory");
    };

    // cluster-wide: everyone's W/shB init done before any reads or remote writes
    asm volatile("barrier.cluster.arrive.aligned;" ::: "memory");
    asm volatile("barrier.cluster.wait.aligned;" ::: "memory");

    stage(0, gxb[0]);
    asm volatile("cp.async.commit_group;" ::: "memory");

    for (int t = 0; t < TT; t++) {
        // matches previous step's end-of-step arrive: all h(t-1) frags delivered
        if (t > 0) asm volatile("barrier.cluster.wait.aligned;" ::: "memory");

        float* gxc = gxb[t % 3];
        if (t + 1 < TT) {
            stage(t + 1, gxb[(t + 1) % 3]);
            asm volatile("cp.async.commit_group;" ::: "memory");
            asm volatile("cp.async.wait_group 1;" ::: "memory");
        } else {
            asm volatile("cp.async.wait_group 0;" ::: "memory");
        }
        __syncthreads();   // gx(t) visible to all warps; gates buffer free

        // ---- mma: acc[n8b] = W(A, smem-resident) x h(B), 16 kblks ----
        const uint32_t* shR = shB + (t & 1) * 2048;
        float acc[2][4];
#pragma unroll
        for (int nb = 0; nb < 2; nb++)
#pragma unroll
            for (int q = 0; q < 4; q++) acc[nb][q] = 0.f;

#pragma unroll
        for (int kb = 0; kb < 16; kb++) {
            uint4 av = *(const uint4*)&sW[((kb * 16 + w) * 32 + lane) * 4];
            uint32_t a[4] = {av.x, av.y, av.z, av.w};
            uint2 bv0 = *(const uint2*)&shR[((kb * 2 + 0) * 32 + lane) * 2];
            uint2 bv1 = *(const uint2*)&shR[((kb * 2 + 1) * 32 + lane) * 2];
            mma_f16(acc[0], a, bv0.x, bv0.y);
            mma_f16(acc[1], a, bv1.x, bv1.y);
        }

        // ---- gates -> smem [batch 16][gate slice 256] ----
#pragma unroll
        for (int nb = 0; nb < 2; nb++) {
            int col = w * 16 + g;
            int row = nb * 8 + 2 * c2;
            gates[row * GXS + col]           = acc[nb][0];
            gates[(row + 1) * GXS + col]     = acc[nb][1];
            gates[row * GXS + col + 8]       = acc[nb][2];
            gates[(row + 1) * GXS + col + 8] = acc[nb][3];
        }
        __syncthreads();

        // ---- elementwise update + direct DSMEM h broadcast ----
        const uint32_t bufOffB = ((t + 1) & 1) * 8192;   // bytes into shB region
#pragma unroll
        for (int i = 0; i < 2; i++) {
            int m = rg * 2 + i;
            float4 gx4 = *(const float4*)(gxc + m * GXS + jl * 4);
            float4 gt  = *(const float4*)(gates + m * GXS + jl * 4);
            float ig = sigmoid_fast(gt.x + gx4.x);
            float fg = sigmoid_fast(gt.y + gx4.y);
            float gv = tanh_fast(gt.z + gx4.z);
            float og = sigmoid_fast(gt.w + gx4.w);
            float cn = fg * cst[i] + ig * gv;
            cst[i] = cn;
            float h = og * tanh_fast(cn);

            out[((size_t)(b0 + m) * TT + t) * HH + jg] = h;

            // h -> fp16 B-fragment position (k = jg, n = m) in all 4 CTAs
            int n8b = m >> 3;
            int laneB = (m & 7) * 4 + cU;
            uint32_t idx2 = (((uint32_t)(kblkU * 2 + n8b) * 32 + laneB) * 2 + ridxU) * 2 + hfU;
            uint32_t off = bufOffB + idx2 * 2;
            unsigned short hb = __half_as_ushort(__float2half_rn(h));
#pragma unroll
            for (int d = 0; d < 4; d++)
                asm volatile("st.shared::cluster.u16 [%0], %1;"
                             :: "r"(peerB[d] + off), "h"(hb) : "memory");
        }
        // release this thread's remote h stores; peers wait at top of t+1
        asm volatile("barrier.cluster.arrive.aligned;" ::: "memory");
    }
    // match final arrive; no CTA exits while peers may still write its smem
    asm volatile("barrier.cluster.wait.aligned;" ::: "memory");
}

// ---------------------------------------------------------------------------
// Launch
// ---------------------------------------------------------------------------
extern "C" void kernel_launch(void* const* d_in, const int* in_sizes, int n_in,
                              void* d_out, int out_size)
{
    const float* x     = (const float*)d_in[0];
    const float* W_ih1 = (const float*)d_in[1];
    const float* W_hh1 = (const float*)d_in[2];
    const float* b_ih1 = (const float*)d_in[3];
    const float* b_hh1 = (const float*)d_in[4];
    const float* W_ih2 = (const float*)d_in[5];
    const float* W_hh2 = (const float*)d_in[6];
    const float* b_ih2 = (const float*)d_in[7];
    const float* b_hh2 = (const float*)d_in[8];
    float* out = (float*)d_out;

    // smem: W 128KB + shB 16KB + gx 3*16*GXS*4 + gates 16*GXS*4 = 214,016 B
    const int scan_smem = 32768 * 4 + 4096 * 4 + (48 + 16) * GXS * 4;
    cudaFuncSetAttribute(lstm_scan7,
                         cudaFuncAttributeMaxDynamicSharedMemorySize, scan_smem);

    dim3 ggrid(BT / 128, GG / 64);  // 672 x 16

    // Layer 1
    prep_weights<<<1024, 256>>>(W_ih1, W_hh1, b_ih1, b_hh1, II);
    gemm_gx_tf32<II><<<ggrid, 256>>>(x);
    lstm_scan7<<<(BB / 16) * 4, 512, scan_smem>>>(nullptr);    // 128 CTAs (32 clusters)

    // Layer 2
    prep_weights<<<1024, 256>>>(W_ih2, W_hh2, b_ih2, b_hh2, HH);
    gemm_gx_tf32<HH><<<ggrid, 256>>>(nullptr);
    lstm_scan7<<<(BB / 16) * 4, 512, scan_smem>>>(out);
}

// round 12
// speedup vs baseline: 1.6258x; 1.0375x over previous
#include <cuda_runtime.h>
#include <cuda_fp16.h>
#include <math.h>
#include <stdint.h>

// Problem constants
#define BB 512
#define TT 168
#define II 64
#define HH 256
#define GG 1024   // 4*H
#define BT (BB*TT)
#define GXS 260   // staged gx / gates smem row stride (floats)

// ---------------------------------------------------------------------------
// Scratch (device globals: allocation-free rule)
// ---------------------------------------------------------------------------
__device__ float g_gx[(size_t)BT * GG];   // gate pre-activations, interleaved gate layout
__device__ float g_out1[(size_t)BT * HH]; // layer-1 hidden outputs
__device__ float g_WT[HH * GG];           // W_ih transposed+interleaved (GEMM B)
__device__ __half g_WhhPh[HH * GG];       // W_hh fp16, per-rank A-fragment layout (see prep)
__device__ float g_bias[GG];              // b_ih+b_hh, interleaved

// Interleaving: column n = j*4+q maps to raw gate row r = q*256 + j
// (q: 0=i, 1=f, 2=g, 3=o).

// ---------------------------------------------------------------------------
// tf32 / fp16 mma / activation helpers
// ---------------------------------------------------------------------------
__device__ __forceinline__ uint32_t f2tf32(float x) {
    uint32_t r;
    asm("cvt.rna.tf32.f32 %0, %1;" : "=r"(r) : "f"(x));
    return r;
}

__device__ __forceinline__ void mma_tf32(float* c, const uint32_t* a, uint32_t b0, uint32_t b1) {
    asm volatile(
        "mma.sync.aligned.m16n8k8.row.col.f32.tf32.tf32.f32 "
        "{%0,%1,%2,%3}, {%4,%5,%6,%7}, {%8,%9}, {%0,%1,%2,%3};"
        : "+f"(c[0]), "+f"(c[1]), "+f"(c[2]), "+f"(c[3])
        : "r"(a[0]), "r"(a[1]), "r"(a[2]), "r"(a[3]), "r"(b0), "r"(b1));
}

// m16n8k16 fp16 inputs, fp32 accumulate
__device__ __forceinline__ void mma_f16(float* c, const uint32_t* a, uint32_t b0, uint32_t b1) {
    asm volatile(
        "mma.sync.aligned.m16n8k16.row.col.f32.f16.f16.f32 "
        "{%0,%1,%2,%3}, {%4,%5,%6,%7}, {%8,%9}, {%0,%1,%2,%3};"
        : "+f"(c[0]), "+f"(c[1]), "+f"(c[2]), "+f"(c[3])
        : "r"(a[0]), "r"(a[1]), "r"(a[2]), "r"(a[3]), "r"(b0), "r"(b1));
}

__device__ __forceinline__ float sigmoid_fast(float x) {
    return __fdividef(1.f, 1.f + __expf(-x));
}
__device__ __forceinline__ float tanh_fast(float x) {
    float xc = fminf(fmaxf(x, -15.f), 15.f);
    float e = __expf(-2.f * xc);
    return __fdividef(1.f - e, 1.f + e);
}

// ---------------------------------------------------------------------------
// Weight prep: transpose + gate-interleave + bias combine + scan W permute.
// Scan W fp16 layout = m16n8k16 A fragments (gates = M, k = K), sliced for
// a 4-CTA cluster: rank = n>>8 owns gate slice [rank*256, rank*256+256);
// within a slice, warp ws = (n>>4)&15 owns one m16 block.
//   m = n&15: gA = m&7, rlo = m>>3; kin = k&15: cA = (kin&7)>>1, khi = kin>>3,
//   hf = kin&1; ridx = rlo + 2*khi; laneA = (gA<<2)|cA.
//   uint4 index = ((rank*16 + kblk)*16 + ws)*32 + laneA   (kblk = k>>4)
// ---------------------------------------------------------------------------
__global__ void prep_weights(const float* __restrict__ W_ih,
                             const float* __restrict__ W_hh,
                             const float* __restrict__ b_ih,
                             const float* __restrict__ b_hh,
                             int K)
{
    int idx = blockIdx.x * 256 + threadIdx.x;  // 0 .. 256*1024-1
    int n = idx & (GG - 1);
    int k = idx >> 10;
    int j = n >> 2;
    int q = n & 3;
    int r = q * HH + j;
    if (k < K) g_WT[k * GG + n] = W_ih[r * K + k];

    {
        float wv = W_hh[r * HH + k];
        int rank = n >> 8;
        int ws   = (n >> 4) & 15;
        int m    = n & 15;
        int gA = m & 7, rlo = m >> 3;
        int kblk = k >> 4, kin = k & 15;
        int cA = (kin & 7) >> 1, khi = kin >> 3, hf = kin & 1;
        int ridx = rlo + 2 * khi;
        int laneA = (gA << 2) | cA;
        size_t u4 = ((size_t)(rank * 16 + kblk) * 16 + ws) * 32 + laneA;
        g_WhhPh[(u4 * 4 + ridx) * 2 + hf] = __float2half_rn(wv);
    }
    if (k == 0) g_bias[n] = b_ih[r] + b_hh[r];
}

// ---------------------------------------------------------------------------
// Feed-forward GEMM (tensor cores, tf32): unchanged (validated R2-R11).
// ---------------------------------------------------------------------------
template <int K>
__global__ __launch_bounds__(256)
void gemm_gx_tf32(const float* __restrict__ X_in)
{
    const float* X = X_in ? X_in : (const float*)g_out1;
    constexpr int KT = K / 32;

    __shared__ uint32_t sA[2][4096];
    __shared__ uint32_t sB[2][2048];

    const int tid  = threadIdx.x;
    const int warp = tid >> 5;
    const int lane = tid & 31;
    const int m0 = blockIdx.x * 128;
    const int n0 = blockIdx.y * 64;
    const int wmb = (warp >> 1) * 2;
    const int wnb = (warp & 1) * 4;

    float acc[2][4][4];
#pragma unroll
    for (int i = 0; i < 2; i++)
#pragma unroll
        for (int j = 0; j < 4; j++)
#pragma unroll
            for (int q = 0; q < 4; q++) acc[i][j][q] = 0.f;

    float4 av[4];
    float4 bv[2];

    auto ldg_tile = [&](int kt) {
#pragma unroll
        for (int i = 0; i < 4; i++) {
            int v = tid + 256 * i;
            int row = v >> 3;
            int kc = (v & 7) * 4;
            av[i] = *(const float4*)(X + (size_t)(m0 + row) * K + kt * 32 + kc);
        }
#pragma unroll
        for (int i = 0; i < 2; i++) {
            int v = tid + 256 * i;
            int row = v >> 4;
            int nc = (v & 15) * 4;
            bv[i] = *(const float4*)(g_WT + (size_t)(kt * 32 + row) * GG + n0 + nc);
        }
    };

    auto sts_tile = [&](int buf) {
#pragma unroll
        for (int i = 0; i < 4; i++) {
            int v = tid + 256 * i;
            int row = v >> 3;
            int kc0 = (v & 7) * 4;
            int mblk = row >> 4, mr = row & 15;
            float f[4] = {av[i].x, av[i].y, av[i].z, av[i].w};
#pragma unroll
            for (int j = 0; j < 4; j++) {
                int kc = kc0 + j;
                int kblk = kc >> 3, kin = kc & 7;
                int t = ((mr & 7) << 2) | (kin & 3);
                int slot = ((kin >> 2) << 1) | (mr >> 3);
                sA[buf][(((kblk << 3) | mblk) << 7) + (t << 2) + slot] = f2tf32(f[j]);
            }
        }
#pragma unroll
        for (int i = 0; i < 2; i++) {
            int v = tid + 256 * i;
            int row = v >> 4;
            int nc0 = (v & 15) * 4;
            int kblk = row >> 3, kin = row & 7;
            float f[4] = {bv[i].x, bv[i].y, bv[i].z, bv[i].w};
#pragma unroll
            for (int j = 0; j < 4; j++) {
                int nc = nc0 + j;
                int nblk = nc >> 3, nin = nc & 7;
                int t = (nin << 2) | (kin & 3);
                int slot = kin >> 2;
                sB[buf][(((kblk << 3) | nblk) << 6) + (t << 1) + slot] = f2tf32(f[j]);
            }
        }
    };

    auto compute = [&](int buf) {
#pragma unroll
        for (int ks = 0; ks < 4; ks++) {
            uint32_t afr[2][4];
            uint32_t bfr[4][2];
#pragma unroll
            for (int mi = 0; mi < 2; mi++) {
                uint4 a = *(const uint4*)&sA[buf][(((ks << 3) | (wmb + mi)) << 7) + (lane << 2)];
                afr[mi][0] = a.x; afr[mi][1] = a.y; afr[mi][2] = a.z; afr[mi][3] = a.w;
            }
#pragma unroll
            for (int ni = 0; ni < 4; ni++) {
                uint2 b = *(const uint2*)&sB[buf][(((ks << 3) | (wnb + ni)) << 6) + (lane << 1)];
                bfr[ni][0] = b.x; bfr[ni][1] = b.y;
            }
#pragma unroll
            for (int mi = 0; mi < 2; mi++)
#pragma unroll
                for (int ni = 0; ni < 4; ni++)
                    mma_tf32(acc[mi][ni], afr[mi], bfr[ni][0], bfr[ni][1]);
        }
    };

    ldg_tile(0);
    sts_tile(0);
    __syncthreads();
#pragma unroll
    for (int kt = 0; kt < KT; kt++) {
        if (kt + 1 < KT) ldg_tile(kt + 1);
        compute(kt & 1);
        if (kt + 1 < KT) sts_tile((kt + 1) & 1);
        __syncthreads();
    }

    const int g = lane >> 2;
    const int cq = lane & 3;
#pragma unroll
    for (int ni = 0; ni < 4; ni++) {
        int gn = n0 + ((wnb + ni) << 3) + cq * 2;
        float bx = g_bias[gn];
        float by = g_bias[gn + 1];
#pragma unroll
        for (int mi = 0; mi < 2; mi++) {
            int gm = m0 + ((wmb + mi) << 4) + g;
            float2 r0 = make_float2(acc[mi][ni][0] + bx, acc[mi][ni][1] + by);
            float2 r1 = make_float2(acc[mi][ni][2] + bx, acc[mi][ni][3] + by);
            *(float2*)(g_gx + (size_t)gm * GG + gn) = r0;
            *(float2*)(g_gx + (size_t)(gm + 8) * GG + gn) = r1;
        }
    }
}

// ---------------------------------------------------------------------------
// Recurrent scan v8: 4-CTA cluster, SMEM-resident W. Changes vs v7:
//  1. update thread owns a COLUMN PAIR (jg, jg+1) x 1 row -> DSMEM h stores
//     packed u32 (2048/CTA vs 4096), out stores become STG.64.
//  2. cluster wait moved to just before the mma (after gx staging + sync):
//     barrier latency hidden behind staging. Hazard audit: shB buf (t+1)&1
//     writes still occur after wait(t); mma(t) reads buf t&1 delivered
//     before peers' step-(t-1) arrive. Unchanged guarantees.
//  3. out STG issued AFTER the cluster arrive (overlaps peer convergence).
// ---------------------------------------------------------------------------
__global__ __launch_bounds__(512, 1) __cluster_dims__(4, 1, 1)
void lstm_scan8(float* __restrict__ out_in)
{
    float* out = out_in ? out_in : (float*)g_out1;

    extern __shared__ float smem_f[];
    uint32_t* sW  = (uint32_t*)smem_f;        // 32768 u32 = 128KB W slice (A-frags)
    uint32_t* shB = sW + 32768;               // 2 x 2048 u32 h B-frags
    float* gx0   = (float*)(shB + 4096);
    float* gxb[3] = { gx0, gx0 + 16 * GXS, gx0 + 32 * GXS };   // 3 x [16][GXS]
    float* gates = gx0 + 48 * GXS;            // [16][GXS]

    const int tid  = threadIdx.x;
    const int w    = tid >> 5;
    const int lane = tid & 31;
    const int g    = lane >> 2;
    const int c2   = lane & 3;

    uint32_t rank;
    asm("mov.u32 %0, %%cluster_ctarank;" : "=r"(rank));
    const int b0 = (blockIdx.x >> 2) * 16;

    // ---- one-time: W slice -> smem; zero h frag buffers ----
    {
        const uint4* Wg = ((const uint4*)g_WhhPh) + (size_t)rank * 8192;
        uint4* sW4 = (uint4*)sW;
        for (int i = tid; i < 8192; i += 512) sW4[i] = Wg[i];
        for (int i = tid; i < 4096; i += 512) shB[i] = 0u;
    }

    // ---- update-phase constants: thread owns cols {jg, jg+1}, row rowU ----
    const int pair = tid & 31;            // column pair index within slice
    const int rowU = tid >> 5;            // batch row 0..15
    const int jl   = pair * 2;            // local h col (even)
    const int jg   = (int)rank * 64 + jl; // global h col (even)
    const int kblkU = jg >> 4;
    const int kinU  = jg & 15;            // even
    const int cU    = (kinU & 7) >> 1;
    const int ridxU = kinU >> 3;
    const int n8bU  = rowU >> 3;
    const int laneBU = (rowU & 7) * 4 + cU;
    const uint32_t idx2U = (((uint32_t)(kblkU * 2 + n8bU) * 32 + laneBU) * 2 + ridxU);
    float cst[2] = {0.f, 0.f};

    // ---- peer shB base addresses (dsmem) ----
    uint32_t shB_local;
    asm("{ .reg .u64 t; cvta.to.shared.u64 t, %1; cvt.u32.u64 %0, t; }"
        : "=r"(shB_local) : "l"((void*)shB));
    uint32_t peerB[4];
#pragma unroll
    for (int d = 0; d < 4; d++)
        asm("mapa.shared::cluster.u32 %0, %1, %2;" : "=r"(peerB[d]) : "r"(shB_local), "r"(d));

    // cp.async: warp w stages row (b0+w)'s 256-float gate slice (1KB)
    auto stage = [&](int t, float* buf) {
        const float* src = g_gx + ((size_t)(b0 + w) * TT + t) * GG + rank * 256;
        uint32_t dst = (uint32_t)__cvta_generic_to_shared(buf + w * GXS);
#pragma unroll
        for (int i = 0; i < 2; i++)
            asm volatile("cp.async.cg.shared.global [%0], [%1], 16;"
                         :: "r"(dst + i * 512 + lane * 16),
                            "l"(src + i * 128 + lane * 4) : "memory");
    };

    // cluster-wide: everyone's W/shB init done before any reads or remote writes
    asm volatile("barrier.cluster.arrive.aligned;" ::: "memory");
    asm volatile("barrier.cluster.wait.aligned;" ::: "memory");

    stage(0, gxb[0]);
    asm volatile("cp.async.commit_group;" ::: "memory");

    for (int t = 0; t < TT; t++) {
        float* gxc = gxb[t % 3];
        if (t + 1 < TT) {
            stage(t + 1, gxb[(t + 1) % 3]);
            asm volatile("cp.async.commit_group;" ::: "memory");
            asm volatile("cp.async.wait_group 1;" ::: "memory");
        } else {
            asm volatile("cp.async.wait_group 0;" ::: "memory");
        }
        __syncthreads();   // gx(t) visible to all warps; gates buffer free

        // h(t-1) delivery barrier — deferred to last moment before the mma
        if (t > 0) asm volatile("barrier.cluster.wait.aligned;" ::: "memory");

        // ---- mma: acc[n8b] = W(A, smem-resident) x h(B), 16 kblks ----
        const uint32_t* shR = shB + (t & 1) * 2048;
        float acc[2][4];
#pragma unroll
        for (int nb = 0; nb < 2; nb++)
#pragma unroll
            for (int q = 0; q < 4; q++) acc[nb][q] = 0.f;

#pragma unroll
        for (int kb = 0; kb < 16; kb++) {
            uint4 av = *(const uint4*)&sW[((kb * 16 + w) * 32 + lane) * 4];
            uint32_t a[4] = {av.x, av.y, av.z, av.w};
            uint2 bv0 = *(const uint2*)&shR[((kb * 2 + 0) * 32 + lane) * 2];
            uint2 bv1 = *(const uint2*)&shR[((kb * 2 + 1) * 32 + lane) * 2];
            mma_f16(acc[0], a, bv0.x, bv0.y);
            mma_f16(acc[1], a, bv1.x, bv1.y);
        }

        // ---- gates -> smem [batch 16][gate slice 256] ----
#pragma unroll
        for (int nb = 0; nb < 2; nb++) {
            int col = w * 16 + g;
            int row = nb * 8 + 2 * c2;
            gates[row * GXS + col]           = acc[nb][0];
            gates[(row + 1) * GXS + col]     = acc[nb][1];
            gates[row * GXS + col + 8]       = acc[nb][2];
            gates[(row + 1) * GXS + col + 8] = acc[nb][3];
        }
        __syncthreads();

        // ---- elementwise update (2 cols x 1 row) + packed DSMEM broadcast ----
        const uint32_t bufOffB = ((t + 1) & 1) * 8192;   // bytes
        float4 gxa = *(const float4*)(gxc + rowU * GXS + jl * 4);
        float4 gxb4 = *(const float4*)(gxc + rowU * GXS + jl * 4 + 4);
        float4 gta = *(const float4*)(gates + rowU * GXS + jl * 4);
        float4 gtb = *(const float4*)(gates + rowU * GXS + jl * 4 + 4);

        // column jg (even, hf=0)
        float ig0 = sigmoid_fast(gta.x + gxa.x);
        float fg0 = sigmoid_fast(gta.y + gxa.y);
        float gv0 = tanh_fast(gta.z + gxa.z);
        float og0 = sigmoid_fast(gta.w + gxa.w);
        float cn0 = fg0 * cst[0] + ig0 * gv0;
        cst[0] = cn0;
        float h0 = og0 * tanh_fast(cn0);
        // column jg+1 (odd, hf=1)
        float ig1 = sigmoid_fast(gtb.x + gxb4.x);
        float fg1 = sigmoid_fast(gtb.y + gxb4.y);
        float gv1 = tanh_fast(gtb.z + gxb4.z);
        float og1 = sigmoid_fast(gtb.w + gxb4.w);
        float cn1 = fg1 * cst[1] + ig1 * gv1;
        cst[1] = cn1;
        float h1 = og1 * tanh_fast(cn1);

        __half2 hp = __floats2half2_rn(h0, h1);   // low half = h0 (hf 0) ✓
        uint32_t hb2 = *(uint32_t*)&hp;
        uint32_t off = bufOffB + idx2U * 4;
#pragma unroll
        for (int d = 0; d < 4; d++)
            asm volatile("st.shared::cluster.u32 [%0], %1;"
                         :: "r"(peerB[d] + off), "r"(hb2) : "memory");

        // release this thread's remote h stores; overlap out STG with peers
        asm volatile("barrier.cluster.arrive.aligned;" ::: "memory");
        *(float2*)(out + ((size_t)(b0 + rowU) * TT + t) * HH + jg) = make_float2(h0, h1);
    }
    // match final arrive; no CTA exits while peers may still write its smem
    asm volatile("barrier.cluster.wait.aligned;" ::: "memory");
}

// ---------------------------------------------------------------------------
// Launch
// ---------------------------------------------------------------------------
extern "C" void kernel_launch(void* const* d_in, const int* in_sizes, int n_in,
                              void* d_out, int out_size)
{
    const float* x     = (const float*)d_in[0];
    const float* W_ih1 = (const float*)d_in[1];
    const float* W_hh1 = (const float*)d_in[2];
    const float* b_ih1 = (const float*)d_in[3];
    const float* b_hh1 = (const float*)d_in[4];
    const float* W_ih2 = (const float*)d_in[5];
    const float* W_hh2 = (const float*)d_in[6];
    const float* b_ih2 = (const float*)d_in[7];
    const float* b_hh2 = (const float*)d_in[8];
    float* out = (float*)d_out;

    // smem: W 128KB + shB 16KB + gx 3*16*GXS*4 + gates 16*GXS*4 = 214,016 B
    const int scan_smem = 32768 * 4 + 4096 * 4 + (48 + 16) * GXS * 4;
    cudaFuncSetAttribute(lstm_scan8,
                         cudaFuncAttributeMaxDynamicSharedMemorySize, scan_smem);

    dim3 ggrid(BT / 128, GG / 64);  // 672 x 16

    // Layer 1
    prep_weights<<<1024, 256>>>(W_ih1, W_hh1, b_ih1, b_hh1, II);
    gemm_gx_tf32<II><<<ggrid, 256>>>(x);
    lstm_scan8<<<(BB / 16) * 4, 512, scan_smem>>>(nullptr);    // 128 CTAs (32 clusters)

    // Layer 2
    prep_weights<<<1024, 256>>>(W_ih2, W_hh2, b_ih2, b_hh2, HH);
    gemm_gx_tf32<HH><<<ggrid, 256>>>(nullptr);
    lstm_scan8<<<(BB / 16) * 4, 512, scan_smem>>>(out);
}

// round 13
// speedup vs baseline: 1.8095x; 1.1129x over previous
#include <cuda_runtime.h>
#include <cuda_fp16.h>
#include <math.h>
#include <stdint.h>

// Problem constants
#define BB 512
#define TT 168
#define II 64
#define HH 256
#define GG 1024   // 4*H
#define BT (BB*TT)
#define GXS 260   // staged gx / gates smem row stride (floats)

// ---------------------------------------------------------------------------
// Scratch (device globals: allocation-free rule)
// ---------------------------------------------------------------------------
__device__ float g_gx[(size_t)BT * GG];   // gate pre-activations, interleaved gate layout
__device__ float g_out1[(size_t)BT * HH]; // layer-1 hidden outputs
__device__ float g_WT[HH * GG];           // W_ih transposed+interleaved (GEMM B)
__device__ __half g_WhhPh[HH * GG];       // W_hh fp16, per-rank A-fragment layout (see prep)
__device__ float g_bias[GG];              // b_ih+b_hh, interleaved

// Interleaving: column n = j*4+q maps to raw gate row r = q*256 + j
// (q: 0=i, 1=f, 2=g, 3=o).

// ---------------------------------------------------------------------------
// tf32 / fp16 mma / activation helpers
// ---------------------------------------------------------------------------
__device__ __forceinline__ uint32_t f2tf32(float x) {
    uint32_t r;
    asm("cvt.rna.tf32.f32 %0, %1;" : "=r"(r) : "f"(x));
    return r;
}

__device__ __forceinline__ void mma_tf32(float* c, const uint32_t* a, uint32_t b0, uint32_t b1) {
    asm volatile(
        "mma.sync.aligned.m16n8k8.row.col.f32.tf32.tf32.f32 "
        "{%0,%1,%2,%3}, {%4,%5,%6,%7}, {%8,%9}, {%0,%1,%2,%3};"
        : "+f"(c[0]), "+f"(c[1]), "+f"(c[2]), "+f"(c[3])
        : "r"(a[0]), "r"(a[1]), "r"(a[2]), "r"(a[3]), "r"(b0), "r"(b1));
}

// m16n8k16 fp16 inputs, fp32 accumulate
__device__ __forceinline__ void mma_f16(float* c, const uint32_t* a, uint32_t b0, uint32_t b1) {
    asm volatile(
        "mma.sync.aligned.m16n8k16.row.col.f32.f16.f16.f32 "
        "{%0,%1,%2,%3}, {%4,%5,%6,%7}, {%8,%9}, {%0,%1,%2,%3};"
        : "+f"(c[0]), "+f"(c[1]), "+f"(c[2]), "+f"(c[3])
        : "r"(a[0]), "r"(a[1]), "r"(a[2]), "r"(a[3]), "r"(b0), "r"(b1));
}

__device__ __forceinline__ float sigmoid_fast(float x) {
    return __fdividef(1.f, 1.f + __expf(-x));
}
__device__ __forceinline__ float tanh_fast(float x) {
    float xc = fminf(fmaxf(x, -15.f), 15.f);
    float e = __expf(-2.f * xc);
    return __fdividef(1.f - e, 1.f + e);
}

// ---------------------------------------------------------------------------
// Weight prep: transpose + gate-interleave + bias combine + scan W permute.
// Scan W fp16 layout = m16n8k16 A fragments (gates = M, k = K), sliced for
// a 4-CTA cluster: rank = n>>8 owns gate slice [rank*256, rank*256+256);
// within a slice, warp ws = (n>>4)&15 owns one m16 block.
//   m = n&15: gA = m&7, rlo = m>>3; kin = k&15: cA = (kin&7)>>1, khi = kin>>3,
//   hf = kin&1; ridx = rlo + 2*khi; laneA = (gA<<2)|cA.
//   uint4 index = ((rank*16 + kblk)*16 + ws)*32 + laneA   (kblk = k>>4)
// ---------------------------------------------------------------------------
__global__ void prep_weights(const float* __restrict__ W_ih,
                             const float* __restrict__ W_hh,
                             const float* __restrict__ b_ih,
                             const float* __restrict__ b_hh,
                             int K)
{
    int idx = blockIdx.x * 256 + threadIdx.x;  // 0 .. 256*1024-1
    int n = idx & (GG - 1);
    int k = idx >> 10;
    int j = n >> 2;
    int q = n & 3;
    int r = q * HH + j;
    if (k < K) g_WT[k * GG + n] = W_ih[r * K + k];

    {
        float wv = W_hh[r * HH + k];
        int rank = n >> 8;
        int ws   = (n >> 4) & 15;
        int m    = n & 15;
        int gA = m & 7, rlo = m >> 3;
        int kblk = k >> 4, kin = k & 15;
        int cA = (kin & 7) >> 1, khi = kin >> 3, hf = kin & 1;
        int ridx = rlo + 2 * khi;
        int laneA = (gA << 2) | cA;
        size_t u4 = ((size_t)(rank * 16 + kblk) * 16 + ws) * 32 + laneA;
        g_WhhPh[(u4 * 4 + ridx) * 2 + hf] = __float2half_rn(wv);
    }
    if (k == 0) g_bias[n] = b_ih[r] + b_hh[r];
}

// ---------------------------------------------------------------------------
// Feed-forward GEMM (tensor cores, tf32): unchanged (validated R2-R12).
// ---------------------------------------------------------------------------
template <int K>
__global__ __launch_bounds__(256)
void gemm_gx_tf32(const float* __restrict__ X_in)
{
    const float* X = X_in ? X_in : (const float*)g_out1;
    constexpr int KT = K / 32;

    __shared__ uint32_t sA[2][4096];
    __shared__ uint32_t sB[2][2048];

    const int tid  = threadIdx.x;
    const int warp = tid >> 5;
    const int lane = tid & 31;
    const int m0 = blockIdx.x * 128;
    const int n0 = blockIdx.y * 64;
    const int wmb = (warp >> 1) * 2;
    const int wnb = (warp & 1) * 4;

    float acc[2][4][4];
#pragma unroll
    for (int i = 0; i < 2; i++)
#pragma unroll
        for (int j = 0; j < 4; j++)
#pragma unroll
            for (int q = 0; q < 4; q++) acc[i][j][q] = 0.f;

    float4 av[4];
    float4 bv[2];

    auto ldg_tile = [&](int kt) {
#pragma unroll
        for (int i = 0; i < 4; i++) {
            int v = tid + 256 * i;
            int row = v >> 3;
            int kc = (v & 7) * 4;
            av[i] = *(const float4*)(X + (size_t)(m0 + row) * K + kt * 32 + kc);
        }
#pragma unroll
        for (int i = 0; i < 2; i++) {
            int v = tid + 256 * i;
            int row = v >> 4;
            int nc = (v & 15) * 4;
            bv[i] = *(const float4*)(g_WT + (size_t)(kt * 32 + row) * GG + n0 + nc);
        }
    };

    auto sts_tile = [&](int buf) {
#pragma unroll
        for (int i = 0; i < 4; i++) {
            int v = tid + 256 * i;
            int row = v >> 3;
            int kc0 = (v & 7) * 4;
            int mblk = row >> 4, mr = row & 15;
            float f[4] = {av[i].x, av[i].y, av[i].z, av[i].w};
#pragma unroll
            for (int j = 0; j < 4; j++) {
                int kc = kc0 + j;
                int kblk = kc >> 3, kin = kc & 7;
                int t = ((mr & 7) << 2) | (kin & 3);
                int slot = ((kin >> 2) << 1) | (mr >> 3);
                sA[buf][(((kblk << 3) | mblk) << 7) + (t << 2) + slot] = f2tf32(f[j]);
            }
        }
#pragma unroll
        for (int i = 0; i < 2; i++) {
            int v = tid + 256 * i;
            int row = v >> 4;
            int nc0 = (v & 15) * 4;
            int kblk = row >> 3, kin = row & 7;
            float f[4] = {bv[i].x, bv[i].y, bv[i].z, bv[i].w};
#pragma unroll
            for (int j = 0; j < 4; j++) {
                int nc = nc0 + j;
                int nblk = nc >> 3, nin = nc & 7;
                int t = (nin << 2) | (kin & 3);
                int slot = kin >> 2;
                sB[buf][(((kblk << 3) | nblk) << 6) + (t << 1) + slot] = f2tf32(f[j]);
            }
        }
    };

    auto compute = [&](int buf) {
#pragma unroll
        for (int ks = 0; ks < 4; ks++) {
            uint32_t afr[2][4];
            uint32_t bfr[4][2];
#pragma unroll
            for (int mi = 0; mi < 2; mi++) {
                uint4 a = *(const uint4*)&sA[buf][(((ks << 3) | (wmb + mi)) << 7) + (lane << 2)];
                afr[mi][0] = a.x; afr[mi][1] = a.y; afr[mi][2] = a.z; afr[mi][3] = a.w;
            }
#pragma unroll
            for (int ni = 0; ni < 4; ni++) {
                uint2 b = *(const uint2*)&sB[buf][(((ks << 3) | (wnb + ni)) << 6) + (lane << 1)];
                bfr[ni][0] = b.x; bfr[ni][1] = b.y;
            }
#pragma unroll
            for (int mi = 0; mi < 2; mi++)
#pragma unroll
                for (int ni = 0; ni < 4; ni++)
                    mma_tf32(acc[mi][ni], afr[mi], bfr[ni][0], bfr[ni][1]);
        }
    };

    ldg_tile(0);
    sts_tile(0);
    __syncthreads();
#pragma unroll
    for (int kt = 0; kt < KT; kt++) {
        if (kt + 1 < KT) ldg_tile(kt + 1);
        compute(kt & 1);
        if (kt + 1 < KT) sts_tile((kt + 1) & 1);
        __syncthreads();
    }

    const int g = lane >> 2;
    const int cq = lane & 3;
#pragma unroll
    for (int ni = 0; ni < 4; ni++) {
        int gn = n0 + ((wnb + ni) << 3) + cq * 2;
        float bx = g_bias[gn];
        float by = g_bias[gn + 1];
#pragma unroll
        for (int mi = 0; mi < 2; mi++) {
            int gm = m0 + ((wmb + mi) << 4) + g;
            float2 r0 = make_float2(acc[mi][ni][0] + bx, acc[mi][ni][1] + by);
            float2 r1 = make_float2(acc[mi][ni][2] + bx, acc[mi][ni][3] + by);
            *(float2*)(g_gx + (size_t)gm * GG + gn) = r0;
            *(float2*)(g_gx + (size_t)(gm + 8) * GG + gn) = r1;
        }
    }
}

// ---------------------------------------------------------------------------
// Recurrent scan v9: 4-CTA cluster, W **REGISTER-resident** (was SMEM in v8).
// Each warp's W slice = 16 kblk x one m16 A-fragment = 16 x uint4 = 64 u32
// registers, loaded ONCE from gmem (time-invariant). The mma loop now issues
// only 2 LDS.64 (h frags) per kblk -> per-step smem crossbar roughly halved
// and the HMMA issue path no longer waits on W LDS latency.
// Everything else identical to v8 (passing): cluster h exchange via packed
// st.shared::cluster.u32, deferred cluster wait, gx triple-buffer.
// ---------------------------------------------------------------------------
__global__ __launch_bounds__(512, 1) __cluster_dims__(4, 1, 1)
void lstm_scan9(float* __restrict__ out_in)
{
    float* out = out_in ? out_in : (float*)g_out1;

    extern __shared__ float smem_f[];
    uint32_t* shB = (uint32_t*)smem_f;        // 2 x 2048 u32 h B-frags
    float* gx0   = (float*)(shB + 4096);
    float* gxb[3] = { gx0, gx0 + 16 * GXS, gx0 + 32 * GXS };   // 3 x [16][GXS]
    float* gates = gx0 + 48 * GXS;            // [16][GXS]

    const int tid  = threadIdx.x;
    const int w    = tid >> 5;
    const int lane = tid & 31;
    const int g    = lane >> 2;
    const int c2   = lane & 3;

    uint32_t rank;
    asm("mov.u32 %0, %%cluster_ctarank;" : "=r"(rank));
    const int b0 = (blockIdx.x >> 2) * 16;

    // ---- one-time: W slice -> REGISTERS (64 u32/thread); zero h buffers ----
    uint4 wr[16];
    {
        const uint4* Wg = (const uint4*)g_WhhPh;
#pragma unroll
        for (int kb = 0; kb < 16; kb++)
            wr[kb] = Wg[((size_t)((int)rank * 16 + kb) * 16 + w) * 32 + lane];
        for (int i = tid; i < 4096; i += 512) shB[i] = 0u;
    }

    // ---- update-phase constants: thread owns cols {jg, jg+1}, row rowU ----
    const int pair = tid & 31;            // column pair index within slice
    const int rowU = tid >> 5;            // batch row 0..15
    const int jl   = pair * 2;            // local h col (even)
    const int jg   = (int)rank * 64 + jl; // global h col (even)
    const int kblkU = jg >> 4;
    const int kinU  = jg & 15;            // even
    const int cU    = (kinU & 7) >> 1;
    const int ridxU = kinU >> 3;
    const int n8bU  = rowU >> 3;
    const int laneBU = (rowU & 7) * 4 + cU;
    const uint32_t idx2U = (((uint32_t)(kblkU * 2 + n8bU) * 32 + laneBU) * 2 + ridxU);
    float cst[2] = {0.f, 0.f};

    // ---- peer shB base addresses (dsmem) ----
    uint32_t shB_local;
    asm("{ .reg .u64 t; cvta.to.shared.u64 t, %1; cvt.u32.u64 %0, t; }"
        : "=r"(shB_local) : "l"((void*)shB));
    uint32_t peerB[4];
#pragma unroll
    for (int d = 0; d < 4; d++)
        asm("mapa.shared::cluster.u32 %0, %1, %2;" : "=r"(peerB[d]) : "r"(shB_local), "r"(d));

    // cp.async: warp w stages row (b0+w)'s 256-float gate slice (1KB)
    auto stage = [&](int t, float* buf) {
        const float* src = g_gx + ((size_t)(b0 + w) * TT + t) * GG + rank * 256;
        uint32_t dst = (uint32_t)__cvta_generic_to_shared(buf + w * GXS);
#pragma unroll
        for (int i = 0; i < 2; i++)
            asm volatile("cp.async.cg.shared.global [%0], [%1], 16;"
                         :: "r"(dst + i * 512 + lane * 16),
                            "l"(src + i * 128 + lane * 4) : "memory");
    };

    // cluster-wide: everyone's shB init done before any remote writes
    asm volatile("barrier.cluster.arrive.aligned;" ::: "memory");
    asm volatile("barrier.cluster.wait.aligned;" ::: "memory");

    stage(0, gxb[0]);
    asm volatile("cp.async.commit_group;" ::: "memory");

    for (int t = 0; t < TT; t++) {
        float* gxc = gxb[t % 3];
        if (t + 1 < TT) {
            stage(t + 1, gxb[(t + 1) % 3]);
            asm volatile("cp.async.commit_group;" ::: "memory");
            asm volatile("cp.async.wait_group 1;" ::: "memory");
        } else {
            asm volatile("cp.async.wait_group 0;" ::: "memory");
        }
        __syncthreads();   // gx(t) visible to all warps; gates buffer free

        // h(t-1) delivery barrier — deferred to last moment before the mma
        if (t > 0) asm volatile("barrier.cluster.wait.aligned;" ::: "memory");

        // ---- mma: acc[n8b] = W(A, registers) x h(B from smem), 16 kblks ----
        const uint32_t* shR = shB + (t & 1) * 2048;
        float acc[2][4];
#pragma unroll
        for (int nb = 0; nb < 2; nb++)
#pragma unroll
            for (int q = 0; q < 4; q++) acc[nb][q] = 0.f;

#pragma unroll
        for (int kb = 0; kb < 16; kb++) {
            uint32_t a[4] = {wr[kb].x, wr[kb].y, wr[kb].z, wr[kb].w};
            uint2 bv0 = *(const uint2*)&shR[((kb * 2 + 0) * 32 + lane) * 2];
            uint2 bv1 = *(const uint2*)&shR[((kb * 2 + 1) * 32 + lane) * 2];
            mma_f16(acc[0], a, bv0.x, bv0.y);
            mma_f16(acc[1], a, bv1.x, bv1.y);
        }

        // ---- gates -> smem [batch 16][gate slice 256] ----
#pragma unroll
        for (int nb = 0; nb < 2; nb++) {
            int col = w * 16 + g;
            int row = nb * 8 + 2 * c2;
            gates[row * GXS + col]           = acc[nb][0];
            gates[(row + 1) * GXS + col]     = acc[nb][1];
            gates[row * GXS + col + 8]       = acc[nb][2];
            gates[(row + 1) * GXS + col + 8] = acc[nb][3];
        }
        __syncthreads();

        // ---- elementwise update (2 cols x 1 row) + packed DSMEM broadcast ----
        const uint32_t bufOffB = ((t + 1) & 1) * 8192;   // bytes
        float4 gxa = *(const float4*)(gxc + rowU * GXS + jl * 4);
        float4 gxb4 = *(const float4*)(gxc + rowU * GXS + jl * 4 + 4);
        float4 gta = *(const float4*)(gates + rowU * GXS + jl * 4);
        float4 gtb = *(const float4*)(gates + rowU * GXS + jl * 4 + 4);

        // column jg (even, hf=0)
        float ig0 = sigmoid_fast(gta.x + gxa.x);
        float fg0 = sigmoid_fast(gta.y + gxa.y);
        float gv0 = tanh_fast(gta.z + gxa.z);
        float og0 = sigmoid_fast(gta.w + gxa.w);
        float cn0 = fg0 * cst[0] + ig0 * gv0;
        cst[0] = cn0;
        float h0 = og0 * tanh_fast(cn0);
        // column jg+1 (odd, hf=1)
        float ig1 = sigmoid_fast(gtb.x + gxb4.x);
        float fg1 = sigmoid_fast(gtb.y + gxb4.y);
        float gv1 = tanh_fast(gtb.z + gxb4.z);
        float og1 = sigmoid_fast(gtb.w + gxb4.w);
        float cn1 = fg1 * cst[1] + ig1 * gv1;
        cst[1] = cn1;
        float h1 = og1 * tanh_fast(cn1);

        __half2 hp = __floats2half2_rn(h0, h1);   // low half = h0 (hf 0) ✓
        uint32_t hb2 = *(uint32_t*)&hp;
        uint32_t off = bufOffB + idx2U * 4;
#pragma unroll
        for (int d = 0; d < 4; d++)
            asm volatile("st.shared::cluster.u32 [%0], %1;"
                         :: "r"(peerB[d] + off), "r"(hb2) : "memory");

        // release this thread's remote h stores; overlap out STG with peers
        asm volatile("barrier.cluster.arrive.aligned;" ::: "memory");
        *(float2*)(out + ((size_t)(b0 + rowU) * TT + t) * HH + jg) = make_float2(h0, h1);
    }
    // match final arrive; no CTA exits while peers may still write its smem
    asm volatile("barrier.cluster.wait.aligned;" ::: "memory");
}

// ---------------------------------------------------------------------------
// Launch
// ---------------------------------------------------------------------------
extern "C" void kernel_launch(void* const* d_in, const int* in_sizes, int n_in,
                              void* d_out, int out_size)
{
    const float* x     = (const float*)d_in[0];
    const float* W_ih1 = (const float*)d_in[1];
    const float* W_hh1 = (const float*)d_in[2];
    const float* b_ih1 = (const float*)d_in[3];
    const float* b_hh1 = (const float*)d_in[4];
    const float* W_ih2 = (const float*)d_in[5];
    const float* W_hh2 = (const float*)d_in[6];
    const float* b_ih2 = (const float*)d_in[7];
    const float* b_hh2 = (const float*)d_in[8];
    float* out = (float*)d_out;

    // smem: shB 16KB + gx 3*16*GXS*4 + gates 16*GXS*4 = 82,944 B
    const int scan_smem = 4096 * 4 + (48 + 16) * GXS * 4;
    cudaFuncSetAttribute(lstm_scan9,
                         cudaFuncAttributeMaxDynamicSharedMemorySize, scan_smem);

    dim3 ggrid(BT / 128, GG / 64);  // 672 x 16

    // Layer 1
    prep_weights<<<1024, 256>>>(W_ih1, W_hh1, b_ih1, b_hh1, II);
    gemm_gx_tf32<II><<<ggrid, 256>>>(x);
    lstm_scan9<<<(BB / 16) * 4, 512, scan_smem>>>(nullptr);    // 128 CTAs (32 clusters)

    // Layer 2
    prep_weights<<<1024, 256>>>(W_ih2, W_hh2, b_ih2, b_hh2, HH);
    gemm_gx_tf32<HH><<<ggrid, 256>>>(nullptr);
    lstm_scan9<<<(BB / 16) * 4, 512, scan_smem>>>(out);
}

// round 15
// speedup vs baseline: 2.5765x; 1.4239x over previous
#include <cuda_runtime.h>
#include <cuda_fp16.h>
#include <math.h>
#include <stdint.h>

// Problem constants
#define BB 512
#define TT 168
#define II 64
#define HH 256
#define GG 1024   // 4*H
#define BT (BB*TT)
#define GXS 260   // staged gx / gates smem row stride (floats)

// ---------------------------------------------------------------------------
// Scratch (device globals: allocation-free rule)
// ---------------------------------------------------------------------------
__device__ float g_gx[(size_t)BT * GG];   // gate pre-activations, interleaved gate layout
__device__ float g_out1[(size_t)BT * HH]; // layer-1 hidden outputs
__device__ __half g_WTh[HH * GG];         // W_ih transposed+interleaved fp16 (GEMM B) [k][n]
__device__ __half g_WhhPh[HH * GG];       // W_hh fp16, per-rank A-fragment layout (see prep)
__device__ float g_bias[GG];              // b_ih+b_hh, interleaved

// Interleaving: column n = j*4+q maps to raw gate row r = q*256 + j
// (q: 0=i, 1=f, 2=g, 3=o).

// ---------------------------------------------------------------------------
// fp16 mma / activation helpers
// ---------------------------------------------------------------------------
// m16n8k16 fp16 inputs, fp32 accumulate
__device__ __forceinline__ void mma_f16(float* c, const uint32_t* a, uint32_t b0, uint32_t b1) {
    asm volatile(
        "mma.sync.aligned.m16n8k16.row.col.f32.f16.f16.f32 "
        "{%0,%1,%2,%3}, {%4,%5,%6,%7}, {%8,%9}, {%0,%1,%2,%3};"
        : "+f"(c[0]), "+f"(c[1]), "+f"(c[2]), "+f"(c[3])
        : "r"(a[0]), "r"(a[1]), "r"(a[2]), "r"(a[3]), "r"(b0), "r"(b1));
}

__device__ __forceinline__ float sigmoid_fast(float x) {
    return __fdividef(1.f, 1.f + __expf(-x));
}
__device__ __forceinline__ float tanh_fast(float x) {
    float xc = fminf(fmaxf(x, -15.f), 15.f);
    float e = __expf(-2.f * xc);
    return __fdividef(1.f - e, 1.f + e);
}

__device__ __forceinline__ uint32_t pack_half2(float a, float b) {
    __half2 h = __floats2half2_rn(a, b);
    return *(uint32_t*)&h;
}

// ---------------------------------------------------------------------------
// Weight prep: transpose + gate-interleave + bias combine + scan W permute.
// GEMM W: fp16 [k][n] (transposed interleaved).
// Scan W fp16 layout = m16n8k16 A fragments (gates = M, k = K), sliced for
// a 4-CTA cluster: rank = n>>8 owns gate slice [rank*256, rank*256+256);
// within a slice, warp ws = (n>>4)&15 owns one m16 block.
//   m = n&15: gA = m&7, rlo = m>>3; kin = k&15: cA = (kin&7)>>1, khi = kin>>3,
//   hf = kin&1; ridx = rlo + 2*khi; laneA = (gA<<2)|cA.
//   uint4 index = ((rank*16 + kblk)*16 + ws)*32 + laneA   (kblk = k>>4)
// ---------------------------------------------------------------------------
__global__ void prep_weights(const float* __restrict__ W_ih,
                             const float* __restrict__ W_hh,
                             const float* __restrict__ b_ih,
                             const float* __restrict__ b_hh,
                             int K)
{
    int idx = blockIdx.x * 256 + threadIdx.x;  // 0 .. 256*1024-1
    int n = idx & (GG - 1);
    int k = idx >> 10;
    int j = n >> 2;
    int q = n & 3;
    int r = q * HH + j;
    if (k < K) g_WTh[k * GG + n] = __float2half_rn(W_ih[r * K + k]);

    {
        float wv = W_hh[r * HH + k];
        int rank = n >> 8;
        int ws   = (n >> 4) & 15;
        int m    = n & 15;
        int gA = m & 7, rlo = m >> 3;
        int kblk = k >> 4, kin = k & 15;
        int cA = (kin & 7) >> 1, khi = kin >> 3, hf = kin & 1;
        int ridx = rlo + 2 * khi;
        int laneA = (gA << 2) | cA;
        size_t u4 = ((size_t)(rank * 16 + kblk) * 16 + ws) * 32 + laneA;
        g_WhhPh[(u4 * 4 + ridx) * 2 + hf] = __float2half_rn(wv);
    }
    if (k == 0) g_bias[n] = b_ih[r] + b_hh[r];
}

// ---------------------------------------------------------------------------
// Feed-forward GEMM (fp16 m16n8k16, fp32 accumulate):
//   g_gx[M=BT][N=1024] = X[M][K] * g_WTh[K][N] + g_bias
// CTA tile 128(M) x 64(N), k-tile 32 (= 2 kblk16), double-buffered SMEM.
// 8 warps in 4x2 layout, each warp 32x32 (2 m16 x 4 n8 mma tiles).
// Fragment packings identical to the scan-validated mappings:
//   A: lane=(gA<<2)|cA, ridx=rlo+2*khi, hf=kin&1  (R13 W layout)
//   B: lane=(nin<<2)|((kin&7)>>1), ridx=kin>>3, hf=kin&1  (R7 h layout)
// 16 HMMA per 32-k tile per warp (was 32 with tf32 k8).
// ---------------------------------------------------------------------------
template <int K>
__global__ __launch_bounds__(256)
void gemm_gx_f16(const float* __restrict__ X_in)
{
    const float* X = X_in ? X_in : (const float*)g_out1;
    constexpr int KT = K / 32;

    __shared__ uint32_t sA[2][2048];   // 128x32 fp16, A-fragment packed
    __shared__ uint32_t sB[2][1024];   // 32x64 fp16, B-fragment packed

    const int tid  = threadIdx.x;
    const int warp = tid >> 5;
    const int lane = tid & 31;
    const int m0 = blockIdx.x * 128;
    const int n0 = blockIdx.y * 64;
    const int wmb = (warp >> 1) * 2;   // warp's first m16 block (0,2,4,6)
    const int wnb = (warp & 1) * 4;    // warp's first n8 block (0,4)

    float acc[2][4][4];
#pragma unroll
    for (int i = 0; i < 2; i++)
#pragma unroll
        for (int j = 0; j < 4; j++)
#pragma unroll
            for (int q = 0; q < 4; q++) acc[i][j][q] = 0.f;

    float4 av[4];
    uint4  bv;

    // ---- global loads for k-tile kt ----
    auto ldg_tile = [&](int kt) {
#pragma unroll
        for (int i = 0; i < 4; i++) {
            int v = tid + 256 * i;
            int row = v >> 3;               // 0..127
            int kc = (v & 7) * 4;           // 0..28
            av[i] = *(const float4*)(X + (size_t)(m0 + row) * K + kt * 32 + kc);
        }
        {
            int row = tid >> 3;             // k row 0..31
            int nc = (tid & 7) * 8;         // 0..56
            bv = *(const uint4*)((const __half*)g_WTh + (size_t)(kt * 32 + row) * GG + n0 + nc);
        }
    };

    // ---- fragment-packed stores into SMEM buffer ----
    auto sts_tile = [&](int buf) {
#pragma unroll
        for (int i = 0; i < 4; i++) {
            int v = tid + 256 * i;
            int row = v >> 3;
            int kc0 = (v & 7) * 4;          // multiple of 4 -> even k pairs
            int mblk = row >> 4, mr = row & 15;
            int gA = mr & 7, rlo = mr >> 3;
            float f[4] = {av[i].x, av[i].y, av[i].z, av[i].w};
#pragma unroll
            for (int j = 0; j < 4; j += 2) {
                int kc = kc0 + j;
                int kblk = kc >> 4, kin = kc & 15;
                int cA = (kin & 7) >> 1, khi = kin >> 3;
                int ridx = rlo + 2 * khi;
                int laneA = (gA << 2) | cA;
                sA[buf][((kblk * 8 + mblk) * 32 + laneA) * 4 + ridx] =
                    pack_half2(f[j], f[j + 1]);
            }
        }
        {
            int krow = tid >> 3;
            int kblk = krow >> 4, kin = krow & 15;
            int cB = (kin & 7) >> 1, ridx = kin >> 3, hf = kin & 1;
            const __half* hsrc = (const __half*)&bv;
            __half* sBh = (__half*)sB[buf];
            int nblk = tid & 7;             // nc0 = nblk*8 covers exactly one n8 block
#pragma unroll
            for (int j = 0; j < 8; j++) {
                int laneB = (j << 2) | cB;
                sBh[(((kblk * 8 + nblk) * 32 + laneB) * 2 + ridx) * 2 + hf] = hsrc[j];
            }
        }
    };

    // ---- compute one 32-k tile from SMEM buffer ----
    auto compute = [&](int buf) {
#pragma unroll
        for (int ks = 0; ks < 2; ks++) {
            uint32_t afr[2][4];
            uint32_t bfr[4][2];
#pragma unroll
            for (int mi = 0; mi < 2; mi++) {
                uint4 a = *(const uint4*)&sA[buf][((ks * 8 + wmb + mi) * 32 + lane) * 4];
                afr[mi][0] = a.x; afr[mi][1] = a.y; afr[mi][2] = a.z; afr[mi][3] = a.w;
            }
#pragma unroll
            for (int ni = 0; ni < 4; ni++) {
                uint2 b = *(const uint2*)&sB[buf][((ks * 8 + wnb + ni) * 32 + lane) * 2];
                bfr[ni][0] = b.x; bfr[ni][1] = b.y;
            }
#pragma unroll
            for (int mi = 0; mi < 2; mi++)
#pragma unroll
                for (int ni = 0; ni < 4; ni++)
                    mma_f16(acc[mi][ni], afr[mi], bfr[ni][0], bfr[ni][1]);
        }
    };

    ldg_tile(0);
    sts_tile(0);
    __syncthreads();
#pragma unroll
    for (int kt = 0; kt < KT; kt++) {
        if (kt + 1 < KT) ldg_tile(kt + 1);
        compute(kt & 1);
        if (kt + 1 < KT) sts_tile((kt + 1) & 1);
        __syncthreads();
    }

    // ---- epilogue: add bias, write fp32 (C fragment layout same as k8) ----
    const int g = lane >> 2;
    const int cq = lane & 3;
#pragma unroll
    for (int ni = 0; ni < 4; ni++) {
        int gn = n0 + ((wnb + ni) << 3) + cq * 2;
        float bx = g_bias[gn];
        float by = g_bias[gn + 1];
#pragma unroll
        for (int mi = 0; mi < 2; mi++) {
            int gm = m0 + ((wmb + mi) << 4) + g;
            float2 r0 = make_float2(acc[mi][ni][0] + bx, acc[mi][ni][1] + by);
            float2 r1 = make_float2(acc[mi][ni][2] + bx, acc[mi][ni][3] + by);
            *(float2*)(g_gx + (size_t)gm * GG + gn) = r0;
            *(float2*)(g_gx + (size_t)(gm + 8) * GG + gn) = r1;
        }
    }
}

// ---------------------------------------------------------------------------
// Recurrent scan v9 (R13, passing at 1893us — byte-identical revert):
// 4-CTA cluster, W REGISTER-resident (64 u32/thread, loaded once).
// ---------------------------------------------------------------------------
__global__ __launch_bounds__(512, 1) __cluster_dims__(4, 1, 1)
void lstm_scan9(float* __restrict__ out_in)
{
    float* out = out_in ? out_in : (float*)g_out1;

    extern __shared__ float smem_f[];
    uint32_t* shB = (uint32_t*)smem_f;        // 2 x 2048 u32 h B-frags
    float* gx0   = (float*)(shB + 4096);
    float* gxb[3] = { gx0, gx0 + 16 * GXS, gx0 + 32 * GXS };   // 3 x [16][GXS]
    float* gates = gx0 + 48 * GXS;            // [16][GXS]

    const int tid  = threadIdx.x;
    const int w    = tid >> 5;
    const int lane = tid & 31;
    const int g    = lane >> 2;
    const int c2   = lane & 3;

    uint32_t rank;
    asm("mov.u32 %0, %%cluster_ctarank;" : "=r"(rank));
    const int b0 = (blockIdx.x >> 2) * 16;

    // ---- one-time: W slice -> REGISTERS (64 u32/thread); zero h buffers ----
    uint4 wr[16];
    {
        const uint4* Wg = (const uint4*)g_WhhPh;
#pragma unroll
        for (int kb = 0; kb < 16; kb++)
            wr[kb] = Wg[((size_t)((int)rank * 16 + kb) * 16 + w) * 32 + lane];
        for (int i = tid; i < 4096; i += 512) shB[i] = 0u;
    }

    // ---- update-phase constants: thread owns cols {jg, jg+1}, row rowU ----
    const int pair = tid & 31;            // column pair index within slice
    const int rowU = tid >> 5;            // batch row 0..15
    const int jl   = pair * 2;            // local h col (even)
    const int jg   = (int)rank * 64 + jl; // global h col (even)
    const int kblkU = jg >> 4;
    const int kinU  = jg & 15;            // even
    const int cU    = (kinU & 7) >> 1;
    const int ridxU = kinU >> 3;
    const int n8bU  = rowU >> 3;
    const int laneBU = (rowU & 7) * 4 + cU;
    const uint32_t idx2U = (((uint32_t)(kblkU * 2 + n8bU) * 32 + laneBU) * 2 + ridxU);
    float cst[2] = {0.f, 0.f};

    // ---- peer shB base addresses (dsmem) ----
    uint32_t shB_local;
    asm("{ .reg .u64 t; cvta.to.shared.u64 t, %1; cvt.u32.u64 %0, t; }"
        : "=r"(shB_local) : "l"((void*)shB));
    uint32_t peerB[4];
#pragma unroll
    for (int d = 0; d < 4; d++)
        asm("mapa.shared::cluster.u32 %0, %1, %2;" : "=r"(peerB[d]) : "r"(shB_local), "r"(d));

    // cp.async: warp w stages row (b0+w)'s 256-float gate slice (1KB)
    auto stage = [&](int t, float* buf) {
        const float* src = g_gx + ((size_t)(b0 + w) * TT + t) * GG + rank * 256;
        uint32_t dst = (uint32_t)__cvta_generic_to_shared(buf + w * GXS);
#pragma unroll
        for (int i = 0; i < 2; i++)
            asm volatile("cp.async.cg.shared.global [%0], [%1], 16;"
                         :: "r"(dst + i * 512 + lane * 16),
                            "l"(src + i * 128 + lane * 4) : "memory");
    };

    // cluster-wide: everyone's shB init done before any remote writes
    asm volatile("barrier.cluster.arrive.aligned;" ::: "memory");
    asm volatile("barrier.cluster.wait.aligned;" ::: "memory");

    stage(0, gxb[0]);
    asm volatile("cp.async.commit_group;" ::: "memory");

    for (int t = 0; t < TT; t++) {
        float* gxc = gxb[t % 3];
        if (t + 1 < TT) {
            stage(t + 1, gxb[(t + 1) % 3]);
            asm volatile("cp.async.commit_group;" ::: "memory");
            asm volatile("cp.async.wait_group 1;" ::: "memory");
        } else {
            asm volatile("cp.async.wait_group 0;" ::: "memory");
        }
        __syncthreads();   // gx(t) visible to all warps; gates buffer free

        // h(t-1) delivery barrier — deferred to last moment before the mma
        if (t > 0) asm volatile("barrier.cluster.wait.aligned;" ::: "memory");

        // ---- mma: acc[n8b] = W(A, registers) x h(B from smem), 16 kblks ----
        const uint32_t* shR = shB + (t & 1) * 2048;
        float acc[2][4];
#pragma unroll
        for (int nb = 0; nb < 2; nb++)
#pragma unroll
            for (int q = 0; q < 4; q++) acc[nb][q] = 0.f;

#pragma unroll
        for (int kb = 0; kb < 16; kb++) {
            uint32_t a[4] = {wr[kb].x, wr[kb].y, wr[kb].z, wr[kb].w};
            uint2 bv0 = *(const uint2*)&shR[((kb * 2 + 0) * 32 + lane) * 2];
            uint2 bv1 = *(const uint2*)&shR[((kb * 2 + 1) * 32 + lane) * 2];
            mma_f16(acc[0], a, bv0.x, bv0.y);
            mma_f16(acc[1], a, bv1.x, bv1.y);
        }

        // ---- gates -> smem [batch 16][gate slice 256] ----
#pragma unroll
        for (int nb = 0; nb < 2; nb++) {
            int col = w * 16 + g;
            int row = nb * 8 + 2 * c2;
            gates[row * GXS + col]           = acc[nb][0];
            gates[(row + 1) * GXS + col]     = acc[nb][1];
            gates[row * GXS + col + 8]       = acc[nb][2];
            gates[(row + 1) * GXS + col + 8] = acc[nb][3];
        }
        __syncthreads();

        // ---- elementwise update (2 cols x 1 row) + packed DSMEM broadcast ----
        const uint32_t bufOffB = ((t + 1) & 1) * 8192;   // bytes
        float4 gxa = *(const float4*)(gxc + rowU * GXS + jl * 4);
        float4 gxb4 = *(const float4*)(gxc + rowU * GXS + jl * 4 + 4);
        float4 gta = *(const float4*)(gates + rowU * GXS + jl * 4);
        float4 gtb = *(const float4*)(gates + rowU * GXS + jl * 4 + 4);

        // column jg (even, hf=0)
        float ig0 = sigmoid_fast(gta.x + gxa.x);
        float fg0 = sigmoid_fast(gta.y + gxa.y);
        float gv0 = tanh_fast(gta.z + gxa.z);
        float og0 = sigmoid_fast(gta.w + gxa.w);
        float cn0 = fg0 * cst[0] + ig0 * gv0;
        cst[0] = cn0;
        float h0 = og0 * tanh_fast(cn0);
        // column jg+1 (odd, hf=1)
        float ig1 = sigmoid_fast(gtb.x + gxb4.x);
        float fg1 = sigmoid_fast(gtb.y + gxb4.y);
        float gv1 = tanh_fast(gtb.z + gxb4.z);
        float og1 = sigmoid_fast(gtb.w + gxb4.w);
        float cn1 = fg1 * cst[1] + ig1 * gv1;
        cst[1] = cn1;
        float h1 = og1 * tanh_fast(cn1);

        __half2 hp = __floats2half2_rn(h0, h1);   // low half = h0 (hf 0) ✓
        uint32_t hb2 = *(uint32_t*)&hp;
        uint32_t off = bufOffB + idx2U * 4;
#pragma unroll
        for (int d = 0; d < 4; d++)
            asm volatile("st.shared::cluster.u32 [%0], %1;"
                         :: "r"(peerB[d] + off), "r"(hb2) : "memory");

        // release this thread's remote h stores; overlap out STG with peers
        asm volatile("barrier.cluster.arrive.aligned;" ::: "memory");
        *(float2*)(out + ((size_t)(b0 + rowU) * TT + t) * HH + jg) = make_float2(h0, h1);
    }
    // match final arrive; no CTA exits while peers may still write its smem
    asm volatile("barrier.cluster.wait.aligned;" ::: "memory");
}

// ---------------------------------------------------------------------------
// Launch
// ---------------------------------------------------------------------------
extern "C" void kernel_launch(void* const* d_in, const int* in_sizes, int n_in,
                              void* d_out, int out_size)
{
    const float* x     = (const float*)d_in[0];
    const float* W_ih1 = (const float*)d_in[1];
    const float* W_hh1 = (const float*)d_in[2];
    const float* b_ih1 = (const float*)d_in[3];
    const float* b_hh1 = (const float*)d_in[4];
    const float* W_ih2 = (const float*)d_in[5];
    const float* W_hh2 = (const float*)d_in[6];
    const float* b_ih2 = (const float*)d_in[7];
    const float* b_hh2 = (const float*)d_in[8];
    float* out = (float*)d_out;

    // smem: shB 16KB + gx 3*16*GXS*4 + gates 16*GXS*4 = 82,944 B
    const int scan_smem = 4096 * 4 + (48 + 16) * GXS * 4;
    cudaFuncSetAttribute(lstm_scan9,
                         cudaFuncAttributeMaxDynamicSharedMemorySize, scan_smem);

    dim3 ggrid(BT / 128, GG / 64);  // 672 x 16

    // Layer 1
    prep_weights<<<1024, 256>>>(W_ih1, W_hh1, b_ih1, b_hh1, II);
    gemm_gx_f16<II><<<ggrid, 256>>>(x);
    lstm_scan9<<<(BB / 16) * 4, 512, scan_smem>>>(nullptr);    // 128 CTAs (32 clusters)

    // Layer 2
    prep_weights<<<1024, 256>>>(W_ih2, W_hh2, b_ih2, b_hh2, HH);
    gemm_gx_f16<HH><<<ggrid, 256>>>(nullptr);
    lstm_scan9<<<(BB / 16) * 4, 512, scan_smem>>>(out);
}

// round 16
// speedup vs baseline: 3.3046x; 1.2826x over previous
#include <cuda_runtime.h>
#include <cuda_fp16.h>
#include <math.h>
#include <stdint.h>

// Problem constants
#define BB 512
#define TT 168
#define II 64
#define HH 256
#define GG 1024   // 4*H
#define BT (BB*TT)
#define GXS 260   // staged gx / gates smem row stride (floats)

// ---------------------------------------------------------------------------
// Scratch (device globals: allocation-free rule)
// ---------------------------------------------------------------------------
__device__ float  g_gx[(size_t)BT * GG];    // gate pre-activations (fp32)
__device__ __half g_xh[(size_t)BT * II];    // x converted to fp16
__device__ __half g_out1h[(size_t)BT * HH]; // layer-1 hidden outputs (fp16)
__device__ __half g_WTh[HH * GG];           // W_ih transposed+interleaved fp16 [k][n]
__device__ __half g_WhhPh[HH * GG];         // W_hh fp16, per-rank A-fragment layout
__device__ float  g_bias[GG];               // b_ih+b_hh, interleaved

// Interleaving: column n = j*4+q maps to raw gate row r = q*256 + j
// (q: 0=i, 1=f, 2=g, 3=o).

// ---------------------------------------------------------------------------
// fp16 mma / ldmatrix / activation helpers
// ---------------------------------------------------------------------------
__device__ __forceinline__ void mma_f16(float* c, const uint32_t* a, uint32_t b0, uint32_t b1) {
    asm volatile(
        "mma.sync.aligned.m16n8k16.row.col.f32.f16.f16.f32 "
        "{%0,%1,%2,%3}, {%4,%5,%6,%7}, {%8,%9}, {%0,%1,%2,%3};"
        : "+f"(c[0]), "+f"(c[1]), "+f"(c[2]), "+f"(c[3])
        : "r"(a[0]), "r"(a[1]), "r"(a[2]), "r"(a[3]), "r"(b0), "r"(b1));
}

__device__ __forceinline__ void ldmatrix_x4(uint32_t* r, uint32_t saddr) {
    asm volatile("ldmatrix.sync.aligned.m8n8.x4.shared.b16 {%0,%1,%2,%3}, [%4];"
                 : "=r"(r[0]), "=r"(r[1]), "=r"(r[2]), "=r"(r[3]) : "r"(saddr));
}
__device__ __forceinline__ void ldmatrix_x4_trans(uint32_t* r, uint32_t saddr) {
    asm volatile("ldmatrix.sync.aligned.m8n8.x4.trans.shared.b16 {%0,%1,%2,%3}, [%4];"
                 : "=r"(r[0]), "=r"(r[1]), "=r"(r[2]), "=r"(r[3]) : "r"(saddr));
}

__device__ __forceinline__ float sigmoid_fast(float x) {
    return __fdividef(1.f, 1.f + __expf(-x));
}
__device__ __forceinline__ float tanh_fast(float x) {
    float xc = fminf(fmaxf(x, -15.f), 15.f);
    float e = __expf(-2.f * xc);
    return __fdividef(1.f - e, 1.f + e);
}

// ---------------------------------------------------------------------------
// x -> fp16 conversion (once)
// ---------------------------------------------------------------------------
__global__ void convert_x(const float* __restrict__ x)
{
    size_t i = ((size_t)blockIdx.x * 256 + threadIdx.x) * 4;
    float4 v = *(const float4*)(x + i);
    __half2 lo = __floats2half2_rn(v.x, v.y);
    __half2 hi = __floats2half2_rn(v.z, v.w);
    *(__half2*)(g_xh + i)     = lo;
    *(__half2*)(g_xh + i + 2) = hi;
}

// ---------------------------------------------------------------------------
// Weight prep: transpose + gate-interleave + bias combine + scan W permute.
// (unchanged from R15, validated)
// ---------------------------------------------------------------------------
__global__ void prep_weights(const float* __restrict__ W_ih,
                             const float* __restrict__ W_hh,
                             const float* __restrict__ b_ih,
                             const float* __restrict__ b_hh,
                             int K)
{
    int idx = blockIdx.x * 256 + threadIdx.x;  // 0 .. 256*1024-1
    int n = idx & (GG - 1);
    int k = idx >> 10;
    int j = n >> 2;
    int q = n & 3;
    int r = q * HH + j;
    if (k < K) g_WTh[k * GG + n] = __float2half_rn(W_ih[r * K + k]);

    {
        float wv = W_hh[r * HH + k];
        int rank = n >> 8;
        int ws   = (n >> 4) & 15;
        int m    = n & 15;
        int gA = m & 7, rlo = m >> 3;
        int kblk = k >> 4, kin = k & 15;
        int cA = (kin & 7) >> 1, khi = kin >> 3, hf = kin & 1;
        int ridx = rlo + 2 * khi;
        int laneA = (gA << 2) | cA;
        size_t u4 = ((size_t)(rank * 16 + kblk) * 16 + ws) * 32 + laneA;
        g_WhhPh[(u4 * 4 + ridx) * 2 + hf] = __float2half_rn(wv);
    }
    if (k == 0) g_bias[n] = b_ih[r] + b_hh[r];
}

// ---------------------------------------------------------------------------
// Feed-forward GEMM (fp16 m16n8k16, fp32 accumulate, ldmatrix pipeline):
//   g_gx[M=BT][N=1024] = X[M][K](fp16) * g_WTh[K][N](fp16) + g_bias
// CTA tile 128(M) x 64(N), k-tile 32, double-buffered row-major SMEM.
// 8 warps 4x2, each 32x32. A via ldmatrix.x4 (row stride 40 halves),
// B via ldmatrix.x4.trans (row stride 72 halves) — both conflict-free.
// ---------------------------------------------------------------------------
#define SAS 40   // A smem row stride (halves)
#define SBS 72   // B smem row stride (halves)

template <int K>
__global__ __launch_bounds__(256)
void gemm_gx_lm(const __half* __restrict__ X)
{
    constexpr int KT = K / 32;

    __shared__ __half sA[2][128 * SAS];
    __shared__ __half sB[2][32 * SBS];

    const int tid  = threadIdx.x;
    const int warp = tid >> 5;
    const int lane = tid & 31;
    const int m0 = blockIdx.x * 128;
    const int n0 = blockIdx.y * 64;
    const int wmb = (warp >> 1) * 2;   // warp's first m16 block (0,2,4,6)
    const int wnb = (warp & 1) * 4;    // warp's first n8 block (0,4)

    float acc[2][4][4];
#pragma unroll
    for (int i = 0; i < 2; i++)
#pragma unroll
        for (int j = 0; j < 4; j++)
#pragma unroll
            for (int q = 0; q < 4; q++) acc[i][j][q] = 0.f;

    uint4 avu[2], bvu;
    const int arow0 = tid >> 1, aseg0 = tid & 1;    // A: 128 rows x 2 x 16B... (see ldg)
    const int brow = tid >> 3, bseg = tid & 7;      // B: 32 rows x 8 x 16B

    // A tile = 128 x 32 halves = 8KB = 256 thr x 2 x 16B; thread i covers
    // (row = (tid+256*i)>>2, seg = (tid+256*i)&3) with seg in 0..3 (8 halves).
    auto ldg_tile = [&](int kt) {
#pragma unroll
        for (int i = 0; i < 2; i++) {
            int v = tid + 256 * i;
            int row = v >> 2, seg = v & 3;
            avu[i] = *(const uint4*)(X + (size_t)(m0 + row) * K + kt * 32 + seg * 8);
        }
        bvu = *(const uint4*)((const __half*)g_WTh + (size_t)(kt * 32 + brow) * GG + n0 + bseg * 8);
    };

    auto sts_tile = [&](int buf) {
#pragma unroll
        for (int i = 0; i < 2; i++) {
            int v = tid + 256 * i;
            int row = v >> 2, seg = v & 3;
            *(uint4*)&sA[buf][row * SAS + seg * 8] = avu[i];
        }
        *(uint4*)&sB[buf][brow * SBS + bseg * 8] = bvu;
    };

    const int lrow  = lane & 15;
    const int lcol8 = (lane >> 4) * 8;

    auto compute = [&](int buf) {
        uint32_t sAbase = (uint32_t)__cvta_generic_to_shared(&sA[buf][0]);
        uint32_t sBbase = (uint32_t)__cvta_generic_to_shared(&sB[buf][0]);
#pragma unroll
        for (int ks = 0; ks < 2; ks++) {
            uint32_t afr[2][4];
#pragma unroll
            for (int mi = 0; mi < 2; mi++) {
                uint32_t ad = sAbase +
                    (((wmb + mi) * 16 + lrow) * SAS + ks * 16 + lcol8) * 2;
                ldmatrix_x4(afr[mi], ad);
            }
            uint32_t bfr[4];   // [np*2 + ridx... ] r0,r1 = nblk wnb+np*2; r2,r3 = +1
            uint32_t bfr2[4];
            {
                uint32_t bd0 = sBbase + ((ks * 16 + lrow) * SBS + wnb * 8 + lcol8) * 2;
                ldmatrix_x4_trans(bfr, bd0);
                uint32_t bd1 = sBbase + ((ks * 16 + lrow) * SBS + (wnb + 2) * 8 + lcol8) * 2;
                ldmatrix_x4_trans(bfr2, bd1);
            }
#pragma unroll
            for (int mi = 0; mi < 2; mi++) {
                mma_f16(acc[mi][0], afr[mi], bfr[0],  bfr[1]);
                mma_f16(acc[mi][1], afr[mi], bfr[2],  bfr[3]);
                mma_f16(acc[mi][2], afr[mi], bfr2[0], bfr2[1]);
                mma_f16(acc[mi][3], afr[mi], bfr2[2], bfr2[3]);
            }
        }
    };

    ldg_tile(0);
    sts_tile(0);
    __syncthreads();
#pragma unroll
    for (int kt = 0; kt < KT; kt++) {
        if (kt + 1 < KT) ldg_tile(kt + 1);
        compute(kt & 1);
        if (kt + 1 < KT) sts_tile((kt + 1) & 1);
        __syncthreads();
    }

    // ---- epilogue: add bias, write fp32 ----
    const int g = lane >> 2;
    const int cq = lane & 3;
#pragma unroll
    for (int ni = 0; ni < 4; ni++) {
        int gn = n0 + ((wnb + ni) << 3) + cq * 2;
        float bx = g_bias[gn];
        float by = g_bias[gn + 1];
#pragma unroll
        for (int mi = 0; mi < 2; mi++) {
            int gm = m0 + ((wmb + mi) << 4) + g;
            float2 r0 = make_float2(acc[mi][ni][0] + bx, acc[mi][ni][1] + by);
            float2 r1 = make_float2(acc[mi][ni][2] + bx, acc[mi][ni][3] + by);
            *(float2*)(g_gx + (size_t)gm * GG + gn) = r0;
            *(float2*)(g_gx + (size_t)(gm + 8) * GG + gn) = r1;
        }
    }
}

// ---------------------------------------------------------------------------
// Recurrent scan v9 (R13/R15, passing): 4-CTA cluster, W register-resident.
// Only change: output is fp16 (layer 1 -> g_out1h) or fp32 (layer 2 -> out).
// ---------------------------------------------------------------------------
__global__ __launch_bounds__(512, 1) __cluster_dims__(4, 1, 1)
void lstm_scan9(float* __restrict__ outf, __half* __restrict__ outh)
{
    extern __shared__ float smem_f[];
    uint32_t* shB = (uint32_t*)smem_f;        // 2 x 2048 u32 h B-frags
    float* gx0   = (float*)(shB + 4096);
    float* gxb[3] = { gx0, gx0 + 16 * GXS, gx0 + 32 * GXS };   // 3 x [16][GXS]
    float* gates = gx0 + 48 * GXS;            // [16][GXS]

    const int tid  = threadIdx.x;
    const int w    = tid >> 5;
    const int lane = tid & 31;
    const int g    = lane >> 2;
    const int c2   = lane & 3;

    uint32_t rank;
    asm("mov.u32 %0, %%cluster_ctarank;" : "=r"(rank));
    const int b0 = (blockIdx.x >> 2) * 16;

    // ---- one-time: W slice -> REGISTERS (64 u32/thread); zero h buffers ----
    uint4 wr[16];
    {
        const uint4* Wg = (const uint4*)g_WhhPh;
#pragma unroll
        for (int kb = 0; kb < 16; kb++)
            wr[kb] = Wg[((size_t)((int)rank * 16 + kb) * 16 + w) * 32 + lane];
        for (int i = tid; i < 4096; i += 512) shB[i] = 0u;
    }

    // ---- update-phase constants: thread owns cols {jg, jg+1}, row rowU ----
    const int pair = tid & 31;
    const int rowU = tid >> 5;
    const int jl   = pair * 2;
    const int jg   = (int)rank * 64 + jl;
    const int kblkU = jg >> 4;
    const int kinU  = jg & 15;
    const int cU    = (kinU & 7) >> 1;
    const int ridxU = kinU >> 3;
    const int n8bU  = rowU >> 3;
    const int laneBU = (rowU & 7) * 4 + cU;
    const uint32_t idx2U = (((uint32_t)(kblkU * 2 + n8bU) * 32 + laneBU) * 2 + ridxU);
    float cst[2] = {0.f, 0.f};

    // ---- peer shB base addresses (dsmem) ----
    uint32_t shB_local;
    asm("{ .reg .u64 t; cvta.to.shared.u64 t, %1; cvt.u32.u64 %0, t; }"
        : "=r"(shB_local) : "l"((void*)shB));
    uint32_t peerB[4];
#pragma unroll
    for (int d = 0; d < 4; d++)
        asm("mapa.shared::cluster.u32 %0, %1, %2;" : "=r"(peerB[d]) : "r"(shB_local), "r"(d));

    // cp.async: warp w stages row (b0+w)'s 256-float gate slice (1KB)
    auto stage = [&](int t, float* buf) {
        const float* src = g_gx + ((size_t)(b0 + w) * TT + t) * GG + rank * 256;
        uint32_t dst = (uint32_t)__cvta_generic_to_shared(buf + w * GXS);
#pragma unroll
        for (int i = 0; i < 2; i++)
            asm volatile("cp.async.cg.shared.global [%0], [%1], 16;"
                         :: "r"(dst + i * 512 + lane * 16),
                            "l"(src + i * 128 + lane * 4) : "memory");
    };

    asm volatile("barrier.cluster.arrive.aligned;" ::: "memory");
    asm volatile("barrier.cluster.wait.aligned;" ::: "memory");

    stage(0, gxb[0]);
    asm volatile("cp.async.commit_group;" ::: "memory");

    for (int t = 0; t < TT; t++) {
        float* gxc = gxb[t % 3];
        if (t + 1 < TT) {
            stage(t + 1, gxb[(t + 1) % 3]);
            asm volatile("cp.async.commit_group;" ::: "memory");
            asm volatile("cp.async.wait_group 1;" ::: "memory");
        } else {
            asm volatile("cp.async.wait_group 0;" ::: "memory");
        }
        __syncthreads();

        if (t > 0) asm volatile("barrier.cluster.wait.aligned;" ::: "memory");

        // ---- mma: acc[n8b] = W(A, registers) x h(B from smem), 16 kblks ----
        const uint32_t* shR = shB + (t & 1) * 2048;
        float acc[2][4];
#pragma unroll
        for (int nb = 0; nb < 2; nb++)
#pragma unroll
            for (int q = 0; q < 4; q++) acc[nb][q] = 0.f;

#pragma unroll
        for (int kb = 0; kb < 16; kb++) {
            uint32_t a[4] = {wr[kb].x, wr[kb].y, wr[kb].z, wr[kb].w};
            uint2 bv0 = *(const uint2*)&shR[((kb * 2 + 0) * 32 + lane) * 2];
            uint2 bv1 = *(const uint2*)&shR[((kb * 2 + 1) * 32 + lane) * 2];
            mma_f16(acc[0], a, bv0.x, bv0.y);
            mma_f16(acc[1], a, bv1.x, bv1.y);
        }

        // ---- gates -> smem [batch 16][gate slice 256] ----
#pragma unroll
        for (int nb = 0; nb < 2; nb++) {
            int col = w * 16 + g;
            int row = nb * 8 + 2 * c2;
            gates[row * GXS + col]           = acc[nb][0];
            gates[(row + 1) * GXS + col]     = acc[nb][1];
            gates[row * GXS + col + 8]       = acc[nb][2];
            gates[(row + 1) * GXS + col + 8] = acc[nb][3];
        }
        __syncthreads();

        // ---- elementwise update (2 cols x 1 row) + packed DSMEM broadcast ----
        const uint32_t bufOffB = ((t + 1) & 1) * 8192;
        float4 gxa  = *(const float4*)(gxc + rowU * GXS + jl * 4);
        float4 gxb4 = *(const float4*)(gxc + rowU * GXS + jl * 4 + 4);
        float4 gta  = *(const float4*)(gates + rowU * GXS + jl * 4);
        float4 gtb  = *(const float4*)(gates + rowU * GXS + jl * 4 + 4);

        float ig0 = sigmoid_fast(gta.x + gxa.x);
        float fg0 = sigmoid_fast(gta.y + gxa.y);
        float gv0 = tanh_fast(gta.z + gxa.z);
        float og0 = sigmoid_fast(gta.w + gxa.w);
        float cn0 = fg0 * cst[0] + ig0 * gv0;
        cst[0] = cn0;
        float h0 = og0 * tanh_fast(cn0);

        float ig1 = sigmoid_fast(gtb.x + gxb4.x);
        float fg1 = sigmoid_fast(gtb.y + gxb4.y);
        float gv1 = tanh_fast(gtb.z + gxb4.z);
        float og1 = sigmoid_fast(gtb.w + gxb4.w);
        float cn1 = fg1 * cst[1] + ig1 * gv1;
        cst[1] = cn1;
        float h1 = og1 * tanh_fast(cn1);

        __half2 hp = __floats2half2_rn(h0, h1);   // low half = h0 ✓
        uint32_t hb2 = *(uint32_t*)&hp;
        uint32_t off = bufOffB + idx2U * 4;
#pragma unroll
        for (int d = 0; d < 4; d++)
            asm volatile("st.shared::cluster.u32 [%0], %1;"
                         :: "r"(peerB[d] + off), "r"(hb2) : "memory");

        asm volatile("barrier.cluster.arrive.aligned;" ::: "memory");
        size_t ooff = ((size_t)(b0 + rowU) * TT + t) * HH + jg;
        if (outh) *(__half2*)(outh + ooff) = hp;
        else      *(float2*)(outf + ooff) = make_float2(h0, h1);
    }
    asm volatile("barrier.cluster.wait.aligned;" ::: "memory");
}

// ---------------------------------------------------------------------------
// Launch
// ---------------------------------------------------------------------------
extern "C" void kernel_launch(void* const* d_in, const int* in_sizes, int n_in,
                              void* d_out, int out_size)
{
    const float* x     = (const float*)d_in[0];
    const float* W_ih1 = (const float*)d_in[1];
    const float* W_hh1 = (const float*)d_in[2];
    const float* b_ih1 = (const float*)d_in[3];
    const float* b_hh1 = (const float*)d_in[4];
    const float* W_ih2 = (const float*)d_in[5];
    const float* W_hh2 = (const float*)d_in[6];
    const float* b_ih2 = (const float*)d_in[7];
    const float* b_hh2 = (const float*)d_in[8];
    float* out = (float*)d_out;

    const int scan_smem = 4096 * 4 + (48 + 16) * GXS * 4;   // 82,944 B
    cudaFuncSetAttribute(lstm_scan9,
                         cudaFuncAttributeMaxDynamicSharedMemorySize, scan_smem);

    __half* d_xh;    cudaGetSymbolAddress((void**)&d_xh, g_xh);
    __half* d_out1h; cudaGetSymbolAddress((void**)&d_out1h, g_out1h);

    dim3 ggrid(BT / 128, GG / 64);  // 672 x 16

    // x -> fp16 (BT*II/4/256 blocks)
    convert_x<<<(BT * II) / 4 / 256, 256>>>(x);

    // Layer 1
    prep_weights<<<1024, 256>>>(W_ih1, W_hh1, b_ih1, b_hh1, II);
    gemm_gx_lm<II><<<ggrid, 256>>>(d_xh);
    lstm_scan9<<<(BB / 16) * 4, 512, scan_smem>>>(nullptr, d_out1h);

    // Layer 2
    prep_weights<<<1024, 256>>>(W_ih2, W_hh2, b_ih2, b_hh2, HH);
    gemm_gx_lm<HH><<<ggrid, 256>>>(d_out1h);
    lstm_scan9<<<(BB / 16) * 4, 512, scan_smem>>>(out, nullptr);
}

// round 17
// speedup vs baseline: 3.5057x; 1.0608x over previous
#include <cuda_runtime.h>
#include <cuda_fp16.h>
#include <math.h>
#include <stdint.h>

// Problem constants
#define BB 512
#define TT 168
#define II 64
#define HH 256
#define GG 1024   // 4*H
#define BT (BB*TT)
#define GXS 260   // gates smem row stride (floats)
#define GXH 264   // staged gx smem row stride (halves)

// ---------------------------------------------------------------------------
// Scratch (device globals: allocation-free rule)
// ---------------------------------------------------------------------------
__device__ __half g_gxh[(size_t)BT * GG];   // gate pre-activations (fp16)
__device__ __half g_xh[(size_t)BT * II];    // x converted to fp16
__device__ __half g_out1h[(size_t)BT * HH]; // layer-1 hidden outputs (fp16)
__device__ __half g_WTh[HH * GG];           // W_ih transposed+interleaved fp16 [k][n]
__device__ __half g_WhhPh[HH * GG];         // W_hh fp16, per-rank A-fragment layout
__device__ float  g_bias[GG];               // b_ih+b_hh, interleaved

// Interleaving: column n = j*4+q maps to raw gate row r = q*256 + j
// (q: 0=i, 1=f, 2=g, 3=o).

// ---------------------------------------------------------------------------
// fp16 mma / ldmatrix / activation helpers
// ---------------------------------------------------------------------------
__device__ __forceinline__ void mma_f16(float* c, const uint32_t* a, uint32_t b0, uint32_t b1) {
    asm volatile(
        "mma.sync.aligned.m16n8k16.row.col.f32.f16.f16.f32 "
        "{%0,%1,%2,%3}, {%4,%5,%6,%7}, {%8,%9}, {%0,%1,%2,%3};"
        : "+f"(c[0]), "+f"(c[1]), "+f"(c[2]), "+f"(c[3])
        : "r"(a[0]), "r"(a[1]), "r"(a[2]), "r"(a[3]), "r"(b0), "r"(b1));
}

__device__ __forceinline__ void ldmatrix_x4(uint32_t* r, uint32_t saddr) {
    asm volatile("ldmatrix.sync.aligned.m8n8.x4.shared.b16 {%0,%1,%2,%3}, [%4];"
                 : "=r"(r[0]), "=r"(r[1]), "=r"(r[2]), "=r"(r[3]) : "r"(saddr));
}
__device__ __forceinline__ void ldmatrix_x4_trans(uint32_t* r, uint32_t saddr) {
    asm volatile("ldmatrix.sync.aligned.m8n8.x4.trans.shared.b16 {%0,%1,%2,%3}, [%4];"
                 : "=r"(r[0]), "=r"(r[1]), "=r"(r[2]), "=r"(r[3]) : "r"(saddr));
}

__device__ __forceinline__ float sigmoid_fast(float x) {
    return __fdividef(1.f, 1.f + __expf(-x));
}
__device__ __forceinline__ float tanh_fast(float x) {
    float xc = fminf(fmaxf(x, -15.f), 15.f);
    float e = __expf(-2.f * xc);
    return __fdividef(1.f - e, 1.f + e);
}

// ---------------------------------------------------------------------------
// x -> fp16 conversion (once)
// ---------------------------------------------------------------------------
__global__ void convert_x(const float* __restrict__ x)
{
    size_t i = ((size_t)blockIdx.x * 256 + threadIdx.x) * 4;
    float4 v = *(const float4*)(x + i);
    *(__half2*)(g_xh + i)     = __floats2half2_rn(v.x, v.y);
    *(__half2*)(g_xh + i + 2) = __floats2half2_rn(v.z, v.w);
}

// ---------------------------------------------------------------------------
// Weight prep: transpose + gate-interleave + bias combine + scan W permute.
// (unchanged from R15/R16, validated)
// ---------------------------------------------------------------------------
__global__ void prep_weights(const float* __restrict__ W_ih,
                             const float* __restrict__ W_hh,
                             const float* __restrict__ b_ih,
                             const float* __restrict__ b_hh,
                             int K)
{
    int idx = blockIdx.x * 256 + threadIdx.x;  // 0 .. 256*1024-1
    int n = idx & (GG - 1);
    int k = idx >> 10;
    int j = n >> 2;
    int q = n & 3;
    int r = q * HH + j;
    if (k < K) g_WTh[k * GG + n] = __float2half_rn(W_ih[r * K + k]);

    {
        float wv = W_hh[r * HH + k];
        int rank = n >> 8;
        int ws   = (n >> 4) & 15;
        int m    = n & 15;
        int gA = m & 7, rlo = m >> 3;
        int kblk = k >> 4, kin = k & 15;
        int cA = (kin & 7) >> 1, khi = kin >> 3, hf = kin & 1;
        int ridx = rlo + 2 * khi;
        int laneA = (gA << 2) | cA;
        size_t u4 = ((size_t)(rank * 16 + kblk) * 16 + ws) * 32 + laneA;
        g_WhhPh[(u4 * 4 + ridx) * 2 + hf] = __float2half_rn(wv);
    }
    if (k == 0) g_bias[n] = b_ih[r] + b_hh[r];
}

// ---------------------------------------------------------------------------
// Feed-forward GEMM (fp16 m16n8k16, fp32 accumulate, ldmatrix pipeline):
//   g_gxh[M=BT][N=1024] = X[M][K](fp16) * g_WTh[K][N] + g_bias   (fp16 out)
// Identical to R16 (passing) except the epilogue writes __half2.
// ---------------------------------------------------------------------------
#define SAS 40   // A smem row stride (halves)
#define SBS 72   // B smem row stride (halves)

template <int K>
__global__ __launch_bounds__(256)
void gemm_gx_lm(const __half* __restrict__ X)
{
    constexpr int KT = K / 32;

    __shared__ __half sA[2][128 * SAS];
    __shared__ __half sB[2][32 * SBS];

    const int tid  = threadIdx.x;
    const int warp = tid >> 5;
    const int lane = tid & 31;
    const int m0 = blockIdx.x * 128;
    const int n0 = blockIdx.y * 64;
    const int wmb = (warp >> 1) * 2;
    const int wnb = (warp & 1) * 4;

    float acc[2][4][4];
#pragma unroll
    for (int i = 0; i < 2; i++)
#pragma unroll
        for (int j = 0; j < 4; j++)
#pragma unroll
            for (int q = 0; q < 4; q++) acc[i][j][q] = 0.f;

    uint4 avu[2], bvu;
    const int brow = tid >> 3, bseg = tid & 7;

    auto ldg_tile = [&](int kt) {
#pragma unroll
        for (int i = 0; i < 2; i++) {
            int v = tid + 256 * i;
            int row = v >> 2, seg = v & 3;
            avu[i] = *(const uint4*)(X + (size_t)(m0 + row) * K + kt * 32 + seg * 8);
        }
        bvu = *(const uint4*)((const __half*)g_WTh + (size_t)(kt * 32 + brow) * GG + n0 + bseg * 8);
    };

    auto sts_tile = [&](int buf) {
#pragma unroll
        for (int i = 0; i < 2; i++) {
            int v = tid + 256 * i;
            int row = v >> 2, seg = v & 3;
            *(uint4*)&sA[buf][row * SAS + seg * 8] = avu[i];
        }
        *(uint4*)&sB[buf][brow * SBS + bseg * 8] = bvu;
    };

    const int lrow  = lane & 15;
    const int lcol8 = (lane >> 4) * 8;

    auto compute = [&](int buf) {
        uint32_t sAbase = (uint32_t)__cvta_generic_to_shared(&sA[buf][0]);
        uint32_t sBbase = (uint32_t)__cvta_generic_to_shared(&sB[buf][0]);
#pragma unroll
        for (int ks = 0; ks < 2; ks++) {
            uint32_t afr[2][4];
#pragma unroll
            for (int mi = 0; mi < 2; mi++) {
                uint32_t ad = sAbase +
                    (((wmb + mi) * 16 + lrow) * SAS + ks * 16 + lcol8) * 2;
                ldmatrix_x4(afr[mi], ad);
            }
            uint32_t bfr[4], bfr2[4];
            {
                uint32_t bd0 = sBbase + ((ks * 16 + lrow) * SBS + wnb * 8 + lcol8) * 2;
                ldmatrix_x4_trans(bfr, bd0);
                uint32_t bd1 = sBbase + ((ks * 16 + lrow) * SBS + (wnb + 2) * 8 + lcol8) * 2;
                ldmatrix_x4_trans(bfr2, bd1);
            }
#pragma unroll
            for (int mi = 0; mi < 2; mi++) {
                mma_f16(acc[mi][0], afr[mi], bfr[0],  bfr[1]);
                mma_f16(acc[mi][1], afr[mi], bfr[2],  bfr[3]);
                mma_f16(acc[mi][2], afr[mi], bfr2[0], bfr2[1]);
                mma_f16(acc[mi][3], afr[mi], bfr2[2], bfr2[3]);
            }
        }
    };

    ldg_tile(0);
    sts_tile(0);
    __syncthreads();
#pragma unroll
    for (int kt = 0; kt < KT; kt++) {
        if (kt + 1 < KT) ldg_tile(kt + 1);
        compute(kt & 1);
        if (kt + 1 < KT) sts_tile((kt + 1) & 1);
        __syncthreads();
    }

    // ---- epilogue: add bias, round once to fp16, write __half2 ----
    const int g = lane >> 2;
    const int cq = lane & 3;
#pragma unroll
    for (int ni = 0; ni < 4; ni++) {
        int gn = n0 + ((wnb + ni) << 3) + cq * 2;
        float bx = g_bias[gn];
        float by = g_bias[gn + 1];
#pragma unroll
        for (int mi = 0; mi < 2; mi++) {
            int gm = m0 + ((wmb + mi) << 4) + g;
            *(__half2*)(g_gxh + (size_t)gm * GG + gn) =
                __floats2half2_rn(acc[mi][ni][0] + bx, acc[mi][ni][1] + by);
            *(__half2*)(g_gxh + (size_t)(gm + 8) * GG + gn) =
                __floats2half2_rn(acc[mi][ni][2] + bx, acc[mi][ni][3] + by);
        }
    }
}

// ---------------------------------------------------------------------------
// Recurrent scan v11 (= R16 v9, passing, + fp16 gx staging + split HMMA
// accumulation chains). 4-CTA cluster, W register-resident.
// ---------------------------------------------------------------------------
__global__ __launch_bounds__(512, 1) __cluster_dims__(4, 1, 1)
void lstm_scan11(float* __restrict__ outf, __half* __restrict__ outh)
{
    extern __shared__ float smem_f[];
    uint32_t* shB = (uint32_t*)smem_f;              // 2 x 2048 u32 h B-frags (16KB)
    __half* gx0 = (__half*)(shB + 4096);
    __half* gxb[3] = { gx0, gx0 + 16 * GXH, gx0 + 32 * GXH };   // 3 x [16][GXH] fp16
    float* gates = (float*)(gx0 + 48 * GXH);        // [16][GXS] fp32

    const int tid  = threadIdx.x;
    const int w    = tid >> 5;
    const int lane = tid & 31;
    const int g    = lane >> 2;
    const int c2   = lane & 3;

    uint32_t rank;
    asm("mov.u32 %0, %%cluster_ctarank;" : "=r"(rank));
    const int b0 = (blockIdx.x >> 2) * 16;

    // ---- one-time: W slice -> REGISTERS (64 u32/thread); zero h buffers ----
    uint4 wr[16];
    {
        const uint4* Wg = (const uint4*)g_WhhPh;
#pragma unroll
        for (int kb = 0; kb < 16; kb++)
            wr[kb] = Wg[((size_t)((int)rank * 16 + kb) * 16 + w) * 32 + lane];
        for (int i = tid; i < 4096; i += 512) shB[i] = 0u;
    }

    // ---- update-phase constants: thread owns cols {jg, jg+1}, row rowU ----
    const int pair = tid & 31;
    const int rowU = tid >> 5;
    const int jl   = pair * 2;
    const int jg   = (int)rank * 64 + jl;
    const int kblkU = jg >> 4;
    const int kinU  = jg & 15;
    const int cU    = (kinU & 7) >> 1;
    const int ridxU = kinU >> 3;
    const int n8bU  = rowU >> 3;
    const int laneBU = (rowU & 7) * 4 + cU;
    const uint32_t idx2U = (((uint32_t)(kblkU * 2 + n8bU) * 32 + laneBU) * 2 + ridxU);
    float cst[2] = {0.f, 0.f};

    // ---- peer shB base addresses (dsmem) ----
    uint32_t shB_local;
    asm("{ .reg .u64 t; cvta.to.shared.u64 t, %1; cvt.u32.u64 %0, t; }"
        : "=r"(shB_local) : "l"((void*)shB));
    uint32_t peerB[4];
#pragma unroll
    for (int d = 0; d < 4; d++)
        asm("mapa.shared::cluster.u32 %0, %1, %2;" : "=r"(peerB[d]) : "r"(shB_local), "r"(d));

    // cp.async: warp w stages row (b0+w)'s 256-half gate slice (512B)
    auto stage = [&](int t, __half* buf) {
        const __half* src = g_gxh + ((size_t)(b0 + w) * TT + t) * GG + rank * 256;
        uint32_t dst = (uint32_t)__cvta_generic_to_shared(buf + w * GXH);
        asm volatile("cp.async.cg.shared.global [%0], [%1], 16;"
                     :: "r"(dst + lane * 16), "l"(src + lane * 8) : "memory");
    };

    asm volatile("barrier.cluster.arrive.aligned;" ::: "memory");
    asm volatile("barrier.cluster.wait.aligned;" ::: "memory");

    stage(0, gxb[0]);
    asm volatile("cp.async.commit_group;" ::: "memory");

    for (int t = 0; t < TT; t++) {
        __half* gxc = gxb[t % 3];
        if (t + 1 < TT) {
            stage(t + 1, gxb[(t + 1) % 3]);
            asm volatile("cp.async.commit_group;" ::: "memory");
            asm volatile("cp.async.wait_group 1;" ::: "memory");
        } else {
            asm volatile("cp.async.wait_group 0;" ::: "memory");
        }
        __syncthreads();

        if (t > 0) asm volatile("barrier.cluster.wait.aligned;" ::: "memory");

        // ---- mma: acc[n8b] = W(A, registers) x h(B from smem), 16 kblks.
        //      Two partial accumulators per n8b (even/odd kb) halve the
        //      serial HMMA dependency depth (16 -> 8). ----
        const uint32_t* shR = shB + (t & 1) * 2048;
        float acc[2][4], accB[2][4];
#pragma unroll
        for (int nb = 0; nb < 2; nb++)
#pragma unroll
            for (int q = 0; q < 4; q++) { acc[nb][q] = 0.f; accB[nb][q] = 0.f; }

#pragma unroll
        for (int kb = 0; kb < 16; kb += 2) {
            {
                uint32_t a[4] = {wr[kb].x, wr[kb].y, wr[kb].z, wr[kb].w};
                uint2 bv0 = *(const uint2*)&shR[((kb * 2 + 0) * 32 + lane) * 2];
                uint2 bv1 = *(const uint2*)&shR[((kb * 2 + 1) * 32 + lane) * 2];
                mma_f16(acc[0], a, bv0.x, bv0.y);
                mma_f16(acc[1], a, bv1.x, bv1.y);
            }
            {
                uint32_t a[4] = {wr[kb + 1].x, wr[kb + 1].y, wr[kb + 1].z, wr[kb + 1].w};
                uint2 bv0 = *(const uint2*)&shR[(((kb + 1) * 2 + 0) * 32 + lane) * 2];
                uint2 bv1 = *(const uint2*)&shR[(((kb + 1) * 2 + 1) * 32 + lane) * 2];
                mma_f16(accB[0], a, bv0.x, bv0.y);
                mma_f16(accB[1], a, bv1.x, bv1.y);
            }
        }
#pragma unroll
        for (int nb = 0; nb < 2; nb++)
#pragma unroll
            for (int q = 0; q < 4; q++) acc[nb][q] += accB[nb][q];

        // ---- gates -> smem [batch 16][gate slice 256] ----
#pragma unroll
        for (int nb = 0; nb < 2; nb++) {
            int col = w * 16 + g;
            int row = nb * 8 + 2 * c2;
            gates[row * GXS + col]           = acc[nb][0];
            gates[(row + 1) * GXS + col]     = acc[nb][1];
            gates[row * GXS + col + 8]       = acc[nb][2];
            gates[(row + 1) * GXS + col + 8] = acc[nb][3];
        }
        __syncthreads();

        // ---- elementwise update (2 cols x 1 row) + packed DSMEM broadcast ----
        const uint32_t bufOffB = ((t + 1) & 1) * 8192;
        uint4 gxr = *(const uint4*)(gxc + rowU * GXH + jl * 4);   // 8 halves
        float2 gi0 = __half22float2(*(__half2*)&gxr.x);
        float2 gg0 = __half22float2(*(__half2*)&gxr.y);
        float2 gi1 = __half22float2(*(__half2*)&gxr.z);
        float2 gg1 = __half22float2(*(__half2*)&gxr.w);
        float4 gta = *(const float4*)(gates + rowU * GXS + jl * 4);
        float4 gtb = *(const float4*)(gates + rowU * GXS + jl * 4 + 4);

        float ig0 = sigmoid_fast(gta.x + gi0.x);
        float fg0 = sigmoid_fast(gta.y + gi0.y);
        float gv0 = tanh_fast(gta.z + gg0.x);
        float og0 = sigmoid_fast(gta.w + gg0.y);
        float cn0 = fg0 * cst[0] + ig0 * gv0;
        cst[0] = cn0;
        float h0 = og0 * tanh_fast(cn0);

        float ig1 = sigmoid_fast(gtb.x + gi1.x);
        float fg1 = sigmoid_fast(gtb.y + gi1.y);
        float gv1 = tanh_fast(gtb.z + gg1.x);
        float og1 = sigmoid_fast(gtb.w + gg1.y);
        float cn1 = fg1 * cst[1] + ig1 * gv1;
        cst[1] = cn1;
        float h1 = og1 * tanh_fast(cn1);

        __half2 hp = __floats2half2_rn(h0, h1);
        uint32_t hb2 = *(uint32_t*)&hp;
        uint32_t off = bufOffB + idx2U * 4;
#pragma unroll
        for (int d = 0; d < 4; d++)
            asm volatile("st.shared::cluster.u32 [%0], %1;"
                         :: "r"(peerB[d] + off), "r"(hb2) : "memory");

        asm volatile("barrier.cluster.arrive.aligned;" ::: "memory");
        size_t ooff = ((size_t)(b0 + rowU) * TT + t) * HH + jg;
        if (outh) *(__half2*)(outh + ooff) = hp;
        else      *(float2*)(outf + ooff) = make_float2(h0, h1);
    }
    asm volatile("barrier.cluster.wait.aligned;" ::: "memory");
}

// ---------------------------------------------------------------------------
// Launch
// ---------------------------------------------------------------------------
extern "C" void kernel_launch(void* const* d_in, const int* in_sizes, int n_in,
                              void* d_out, int out_size)
{
    const float* x     = (const float*)d_in[0];
    const float* W_ih1 = (const float*)d_in[1];
    const float* W_hh1 = (const float*)d_in[2];
    const float* b_ih1 = (const float*)d_in[3];
    const float* b_hh1 = (const float*)d_in[4];
    const float* W_ih2 = (const float*)d_in[5];
    const float* W_hh2 = (const float*)d_in[6];
    const float* b_ih2 = (const float*)d_in[7];
    const float* b_hh2 = (const float*)d_in[8];
    float* out = (float*)d_out;

    // smem: shB 16KB + gx 3*16*GXH*2 + gates 16*GXS*4 = 58,368 B
    const int scan_smem = 4096 * 4 + 48 * GXH * 2 + 16 * GXS * 4;
    cudaFuncSetAttribute(lstm_scan11,
                         cudaFuncAttributeMaxDynamicSharedMemorySize, scan_smem);

    __half* d_xh;    cudaGetSymbolAddress((void**)&d_xh, g_xh);
    __half* d_out1h; cudaGetSymbolAddress((void**)&d_out1h, g_out1h);

    dim3 ggrid(BT / 128, GG / 64);  // 672 x 16

    convert_x<<<(BT * II) / 4 / 256, 256>>>(x);

    // Layer 1
    prep_weights<<<1024, 256>>>(W_ih1, W_hh1, b_ih1, b_hh1, II);
    gemm_gx_lm<II><<<ggrid, 256>>>(d_xh);
    lstm_scan11<<<(BB / 16) * 4, 512, scan_smem>>>(nullptr, d_out1h);

    // Layer 2
    prep_weights<<<1024, 256>>>(W_ih2, W_hh2, b_ih2, b_hh2, HH);
    gemm_gx_lm<HH><<<ggrid, 256>>>(d_out1h);
    lstm_scan11<<<(BB / 16) * 4, 512, scan_smem>>>(out, nullptr);
}